// round 2
// baseline (speedup 1.0000x reference)
#include <cuda_runtime.h>
#include <cuda_bf16.h>
#include <math.h>

// ---------------------------------------------------------------------------
// Problem constants (fixed shapes from reference)
// ---------------------------------------------------------------------------
#define BB      2
#define HH      256
#define WW      256
#define CC      256
#define WS_     8
#define SHIFT_  4
#define NHEAD   8
#define HDIM    32
#define NTOK    64            // tokens per window (8*8)
#define NWIN    1024          // windows per image
#define BWIN    (BB*NWIN)     // 2048 total windows
#define MTOK    (BWIN*NTOK)   // 131072 tokens
#define HID     1024
#define QSCALE  0.17677669529663689f  // 1/sqrt(32)

// ---------------------------------------------------------------------------
// Single scratch arena (device global; liveness-based reuse).
//   qin  [0,        33.5M)   live: step1 .. step5
//   kvin [33.5M,    67.1M)   live: step1 .. step3   } same region
//   xn2  [33.5M,    67.1M)   live: step6 .. step7   }
//   q    [67.1M,   100.7M)   live: step2 .. step4   }
//   kv   [100.7M,  167.8M)   live: step3 .. step4   } hid reuses q+kv+attn
//   attn [167.8M,  201.3M)   live: step4 .. step5   }
//   hid  [67.1M,   201.3M)   live: step7 .. step8   } (exactly 134.2M floats)
//   x1   [201.3M,  234.9M)   live: step5 .. step8
// ---------------------------------------------------------------------------
#define OFF_QIN   ((size_t)0)
#define OFF_KVIN  ((size_t)33554432)
#define OFF_XN2   OFF_KVIN
#define OFF_Q     ((size_t)67108864)
#define OFF_HID   OFF_Q
#define OFF_KV    ((size_t)100663296)
#define OFF_ATTN  ((size_t)167772160)
#define OFF_X1    ((size_t)201326592)
#define ARENA_F   ((size_t)234881024)

__device__ float g_arena[ARENA_F];

// ---------------------------------------------------------------------------
// Kernel 1: LayerNorm + shift-roll + window partition.
// One block per window token; computes LN for d=0 (-> qin) and d=1 (-> kvin).
// ---------------------------------------------------------------------------
__global__ __launch_bounds__(256)
void ln_window_kernel(const float* __restrict__ x,
                      const float* __restrict__ g1,
                      const float* __restrict__ b1)
{
    int token = blockIdx.x;            // 0..MTOK-1
    int tid   = threadIdx.x;           // channel 0..255
    int w_idx = token >> 6;
    int n     = token & 63;
    int b     = w_idx >> 10;
    int win   = w_idx & 1023;
    int wh    = win >> 5, wwc = win & 31;
    int r     = n >> 3,  cw  = n & 7;
    int sh = (wh * WS_ + r  + SHIFT_) & (HH - 1);
    int sw = (wwc * WS_ + cw + SHIFT_) & (WW - 1);

    __shared__ float red[16];
    float gg = g1[tid], bcoef = b1[tid];
    int warp = tid >> 5, lane = tid & 31;

    for (int dsel = 0; dsel < 2; dsel++) {
        size_t base = ((((size_t)b * 2 + dsel) * HH + sh) * WW + sw) * CC;
        float v = x[base + tid];
        float s = v, sq = v * v;
        #pragma unroll
        for (int o = 16; o; o >>= 1) {
            s  += __shfl_xor_sync(0xffffffffu, s,  o);
            sq += __shfl_xor_sync(0xffffffffu, sq, o);
        }
        if (lane == 0) { red[warp] = s; red[8 + warp] = sq; }
        __syncthreads();
        if (tid < 32) {
            float a = (tid < 8) ? red[tid]     : 0.f;
            float c = (tid < 8) ? red[8 + tid] : 0.f;
            #pragma unroll
            for (int o = 4; o; o >>= 1) {
                a += __shfl_xor_sync(0xffffffffu, a, o);
                c += __shfl_xor_sync(0xffffffffu, c, o);
            }
            if (tid == 0) { red[0] = a; red[1] = c; }
        }
        __syncthreads();
        float mean = red[0] * (1.f / CC);
        float var  = red[1] * (1.f / CC) - mean * mean;
        float rstd = rsqrtf(var + 1e-5f);
        float outv = (v - mean) * rstd * gg + bcoef;
        if (dsel == 0) g_arena[OFF_QIN  + (size_t)token * CC + tid] = outv;
        else           g_arena[OFF_KVIN + (size_t)token * CC + tid] = outv;
        __syncthreads();
    }
}

// ---------------------------------------------------------------------------
// Kernel 2: LN2 over x1 (image-token order) -> xn2
// ---------------------------------------------------------------------------
__global__ __launch_bounds__(256)
void ln2_kernel(const float* __restrict__ g2, const float* __restrict__ b2)
{
    int token = blockIdx.x;
    int tid   = threadIdx.x;
    __shared__ float red[16];
    size_t base = (size_t)token * CC;
    float v = g_arena[OFF_X1 + base + tid];
    float s = v, sq = v * v;
    #pragma unroll
    for (int o = 16; o; o >>= 1) {
        s  += __shfl_xor_sync(0xffffffffu, s,  o);
        sq += __shfl_xor_sync(0xffffffffu, sq, o);
    }
    int warp = tid >> 5, lane = tid & 31;
    if (lane == 0) { red[warp] = s; red[8 + warp] = sq; }
    __syncthreads();
    if (tid < 32) {
        float a = (tid < 8) ? red[tid]     : 0.f;
        float c = (tid < 8) ? red[8 + tid] : 0.f;
        #pragma unroll
        for (int o = 4; o; o >>= 1) {
            a += __shfl_xor_sync(0xffffffffu, a, o);
            c += __shfl_xor_sync(0xffffffffu, c, o);
        }
        if (tid == 0) { red[0] = a; red[1] = c; }
    }
    __syncthreads();
    float mean = red[0] * (1.f / CC);
    float var  = red[1] * (1.f / CC) - mean * mean;
    float rstd = rsqrtf(var + 1e-5f);
    g_arena[OFF_XN2 + base + tid] = (v - mean) * rstd * g2[tid] + b2[tid];
}

// ---------------------------------------------------------------------------
// Generic tiled GEMM: out[m,j] = sum_k A[m,k] * W[j,k]  (+ mode-specific epilogue)
// BM=BN=64, BK=16, 256 threads, 4x4 micro-tile.
// A and out are selected internally per MODE (no host symbol queries needed).
// MODE 0: qin  -> q     : (acc+bias)*QSCALE
// MODE 1: kvin -> kv    : acc+bias
// MODE 2: attn -> x1    : acc+bias + q_in + shortcut, scattered to image order
// MODE 3: xn2  -> hid   : gelu(acc+bias)   (exact erf gelu)
// MODE 4: hid  -> d_out : acc+bias + x1
// ---------------------------------------------------------------------------
#define BM 64
#define BN 64
#define BK 16

template<int MODE>
__global__ __launch_bounds__(256)
void gemm_kernel(const float* __restrict__ Wt,
                 const float* __restrict__ bias,
                 const float* __restrict__ xsrc,   // mode2: original x
                 float*       __restrict__ dout,   // mode4: harness output
                 int K, int Ncols)
{
    const float* A =
        (MODE == 0) ? (g_arena + OFF_QIN)  :
        (MODE == 1) ? (g_arena + OFF_KVIN) :
        (MODE == 2) ? (g_arena + OFF_ATTN) :
        (MODE == 3) ? (g_arena + OFF_XN2)  :
                      (g_arena + OFF_HID);
    float* out =
        (MODE == 0) ? (g_arena + OFF_Q)    :
        (MODE == 1) ? (g_arena + OFF_KV)   :
        (MODE == 2) ? (g_arena + OFF_X1)   :
        (MODE == 3) ? (g_arena + OFF_HID)  :
                      dout;

    __shared__ float As[BK][BM];
    __shared__ float Bs[BK][BN];

    int tid = threadIdx.x;
    int m0  = blockIdx.y * BM;
    int n0  = blockIdx.x * BN;

    int lr = tid >> 2;            // 0..63 (row within tile)
    int lq = (tid & 3) * 4;       // 0,4,8,12 (k-quad)

    const float* Arow = A  + (size_t)(m0 + lr) * K + lq;
    const float* Wrow = Wt + (size_t)(n0 + lr) * K + lq;

    int ty = tid >> 4;            // 0..15
    int tx = tid & 15;            // 0..15

    float acc[4][4];
    #pragma unroll
    for (int i = 0; i < 4; i++)
        #pragma unroll
        for (int j = 0; j < 4; j++) acc[i][j] = 0.f;

    for (int k0 = 0; k0 < K; k0 += BK) {
        float4 av = *(const float4*)(Arow + k0);
        float4 wv = *(const float4*)(Wrow + k0);
        As[lq + 0][lr] = av.x; As[lq + 1][lr] = av.y;
        As[lq + 2][lr] = av.z; As[lq + 3][lr] = av.w;
        Bs[lq + 0][lr] = wv.x; Bs[lq + 1][lr] = wv.y;
        Bs[lq + 2][lr] = wv.z; Bs[lq + 3][lr] = wv.w;
        __syncthreads();
        #pragma unroll
        for (int kk = 0; kk < BK; kk++) {
            float4 a  = *(const float4*)&As[kk][ty * 4];
            float4 bv = *(const float4*)&Bs[kk][tx * 4];
            acc[0][0] += a.x * bv.x; acc[0][1] += a.x * bv.y;
            acc[0][2] += a.x * bv.z; acc[0][3] += a.x * bv.w;
            acc[1][0] += a.y * bv.x; acc[1][1] += a.y * bv.y;
            acc[1][2] += a.y * bv.z; acc[1][3] += a.y * bv.w;
            acc[2][0] += a.z * bv.x; acc[2][1] += a.z * bv.y;
            acc[2][2] += a.z * bv.z; acc[2][3] += a.z * bv.w;
            acc[3][0] += a.w * bv.x; acc[3][1] += a.w * bv.y;
            acc[3][2] += a.w * bv.z; acc[3][3] += a.w * bv.w;
        }
        __syncthreads();
    }

    int jb = n0 + tx * 4;
    float bx = bias[jb + 0], by = bias[jb + 1], bz = bias[jb + 2], bw = bias[jb + 3];

    #pragma unroll
    for (int i = 0; i < 4; i++) {
        int m = m0 + ty * 4 + i;
        float4 o;
        o.x = acc[i][0] + bx; o.y = acc[i][1] + by;
        o.z = acc[i][2] + bz; o.w = acc[i][3] + bw;

        if (MODE == 0) {
            o.x *= QSCALE; o.y *= QSCALE; o.z *= QSCALE; o.w *= QSCALE;
            *(float4*)(out + (size_t)m * Ncols + jb) = o;
        } else if (MODE == 1) {
            *(float4*)(out + (size_t)m * Ncols + jb) = o;
        } else if (MODE == 2) {
            // scatter to image order + residuals (q_in + shortcut)
            int w_idx = m >> 6, n = m & 63;
            int b = w_idx >> 10, win = w_idx & 1023;
            int wh = win >> 5, wwc = win & 31;
            int r = n >> 3, cw = n & 7;
            int hi = (wh * WS_ + r  + SHIFT_) & (HH - 1);
            int wi = (wwc * WS_ + cw + SHIFT_) & (WW - 1);
            size_t img  = (((size_t)b * HH + hi) * WW + wi) * CC;         // x1 index
            size_t ximg = ((((size_t)b * 2) * HH + hi) * WW + wi) * CC;   // x[:,0] index
            float4 qi = *(const float4*)(g_arena + OFF_QIN + (size_t)m * CC + jb);
            float4 sc = *(const float4*)(xsrc + ximg + jb);
            o.x += qi.x + sc.x; o.y += qi.y + sc.y;
            o.z += qi.z + sc.z; o.w += qi.w + sc.w;
            *(float4*)(out + img + jb) = o;
        } else if (MODE == 3) {
            o.x = o.x * normcdff(o.x);
            o.y = o.y * normcdff(o.y);
            o.z = o.z * normcdff(o.z);
            o.w = o.w * normcdff(o.w);
            *(float4*)(out + (size_t)m * Ncols + jb) = o;
        } else { // MODE 4
            float4 x1v = *(const float4*)(g_arena + OFF_X1 + (size_t)m * CC + jb);
            o.x += x1v.x; o.y += x1v.y; o.z += x1v.z; o.w += x1v.w;
            *(float4*)(out + (size_t)m * Ncols + jb) = o;
        }
    }
}

// ---------------------------------------------------------------------------
// Kernel 3: windowed attention. One block per (window, head), 64 threads,
// each thread owns one query row (full softmax row in registers).
// ---------------------------------------------------------------------------
__global__ __launch_bounds__(64)
void attn_kernel(const float* __restrict__ mask,
                 const float* __restrict__ btab)
{
    int w_idx = blockIdx.x;
    int hh    = blockIdx.y;
    int t     = threadIdx.x;   // query row n

    __shared__ float ksh[64 * 33];
    __shared__ float vsh[64 * 33];
    __shared__ float sbias[225];

    for (int i = t; i < 225; i += 64) sbias[i] = btab[i * NHEAD + hh];

    size_t kvbase = OFF_KV + ((size_t)w_idx * 64 + t) * (2 * CC) + hh * HDIM;
    const float4* kp = (const float4*)(g_arena + kvbase);
    const float4* vp = (const float4*)(g_arena + kvbase + CC);
    #pragma unroll
    for (int q4 = 0; q4 < 8; q4++) {
        float4 kk = kp[q4];
        ksh[t * 33 + q4 * 4 + 0] = kk.x; ksh[t * 33 + q4 * 4 + 1] = kk.y;
        ksh[t * 33 + q4 * 4 + 2] = kk.z; ksh[t * 33 + q4 * 4 + 3] = kk.w;
        float4 vv = vp[q4];
        vsh[t * 33 + q4 * 4 + 0] = vv.x; vsh[t * 33 + q4 * 4 + 1] = vv.y;
        vsh[t * 33 + q4 * 4 + 2] = vv.z; vsh[t * 33 + q4 * 4 + 3] = vv.w;
    }

    float qreg[32];
    size_t qbase = OFF_Q + ((size_t)w_idx * 64 + t) * CC + hh * HDIM;
    const float4* qp = (const float4*)(g_arena + qbase);
    #pragma unroll
    for (int q4 = 0; q4 < 8; q4++) {
        float4 qq = qp[q4];
        qreg[q4 * 4 + 0] = qq.x; qreg[q4 * 4 + 1] = qq.y;
        qreg[q4 * 4 + 2] = qq.z; qreg[q4 * 4 + 3] = qq.w;
    }
    __syncthreads();

    int r1 = t >> 3, c1 = t & 7;
    int win = w_idx & 1023;
    const float* mrow = mask + ((size_t)win * 64 + t) * 64;

    float s[64];
    #pragma unroll
    for (int m = 0; m < 64; m++) {
        float acc = 0.f;
        #pragma unroll
        for (int dd = 0; dd < 32; dd++)
            acc += qreg[dd] * ksh[m * 33 + dd];
        int r2 = m >> 3, c2 = m & 7;
        s[m] = acc + sbias[(r1 - r2 + 7) * 15 + (c1 - c2 + 7)] + mrow[m];
    }

    float mx = -1e30f;
    #pragma unroll
    for (int m = 0; m < 64; m++) mx = fmaxf(mx, s[m]);
    float sum = 0.f;
    #pragma unroll
    for (int m = 0; m < 64; m++) { s[m] = __expf(s[m] - mx); sum += s[m]; }
    float inv = 1.f / sum;

    float* op = g_arena + OFF_ATTN + ((size_t)w_idx * 64 + t) * CC + hh * HDIM;
    #pragma unroll 4
    for (int dd = 0; dd < 32; dd++) {
        float acc = 0.f;
        #pragma unroll
        for (int m = 0; m < 64; m++)
            acc += s[m] * vsh[m * 33 + dd];
        op[dd] = acc * inv;
    }
}

// ---------------------------------------------------------------------------
// Launch — pure kernel launches, nothing else (graph-capture safe).
// ---------------------------------------------------------------------------
extern "C" void kernel_launch(void* const* d_in, const int* in_sizes, int n_in,
                              void* d_out, int out_size)
{
    const float* x     = (const float*)d_in[0];
    const float* maskm = (const float*)d_in[1];
    const float* g1    = (const float*)d_in[2];
    const float* b1    = (const float*)d_in[3];
    const float* qw    = (const float*)d_in[4];
    const float* qb    = (const float*)d_in[5];
    const float* kvw   = (const float*)d_in[6];
    const float* kvb   = (const float*)d_in[7];
    const float* pw    = (const float*)d_in[8];
    const float* pb    = (const float*)d_in[9];
    const float* btab  = (const float*)d_in[10];
    const float* g2    = (const float*)d_in[11];
    const float* b2    = (const float*)d_in[12];
    const float* w1    = (const float*)d_in[13];
    const float* bi1   = (const float*)d_in[14];
    const float* w2    = (const float*)d_in[15];
    const float* bi2   = (const float*)d_in[16];
    float* out = (float*)d_out;

    // 1) LN1 + shift + window partition
    ln_window_kernel<<<MTOK, 256>>>(x, g1, b1);

    // 2) q projection  [131072 x 256] * [256 x 256]^T -> q (scaled)
    gemm_kernel<0><<<dim3(CC / BN, MTOK / BM), 256>>>(qw, qb, nullptr, nullptr, CC, CC);

    // 3) kv projection [131072 x 256] * [512 x 256]^T -> kv
    gemm_kernel<1><<<dim3(2 * CC / BN, MTOK / BM), 256>>>(kvw, kvb, nullptr, nullptr, CC, 2 * CC);

    // 4) windowed attention -> attn
    attn_kernel<<<dim3(BWIN, NHEAD), 64>>>(maskm, btab);

    // 5) p projection + q_in residual + shortcut, scatter to image order -> x1
    gemm_kernel<2><<<dim3(CC / BN, MTOK / BM), 256>>>(pw, pb, x, nullptr, CC, CC);

    // 6) LN2 -> xn2
    ln2_kernel<<<BB * HH * WW, 256>>>(g2, b2);

    // 7) MLP up + exact GELU -> hid
    gemm_kernel<3><<<dim3(HID / BN, MTOK / BM), 256>>>(w1, bi1, nullptr, nullptr, CC, HID);

    // 8) MLP down + x1 residual -> output
    gemm_kernel<4><<<dim3(CC / BN, MTOK / BM), 256>>>(w2, bi2, nullptr, out, HID, CC);
}

// round 6
// speedup vs baseline: 2.0459x; 2.0459x over previous
#include <cuda_runtime.h>
#include <cuda_bf16.h>
#include <math.h>
#include <stdint.h>

// ---------------------------------------------------------------------------
// Problem constants
// ---------------------------------------------------------------------------
#define HHs     256
#define WWs     256
#define CCs     256
#define WS_     8
#define SHIFT_  4
#define MTOK    131072
#define QSCALE  0.17677669529663689f  // 1/sqrt(32)

// ---------------------------------------------------------------------------
// Arena (u32 words). Split tensors = two bf16 planes: hi[E], lo[E].
// ---------------------------------------------------------------------------
#define OFF_QIN_S  ((size_t)0)           // 33.5M  split (window order)
#define OFF_KVIN_S ((size_t)33554432)    // 33.5M  split
#define OFF_Q      ((size_t)67108864)    // 33.5M  fp32
#define OFF_KV     ((size_t)100663296)   // 67.1M  fp32
#define OFF_ATTN_S ((size_t)167772160)   // 33.5M  split
#define OFF_X1     ((size_t)201326592)   // 33.5M  fp32 (image order)
#define OFF_XN2_S  ((size_t)234881024)   // 33.5M  split
#define OFF_HID_S  ((size_t)268435456)   // 134.2M split
#define OFF_W      ((size_t)402653184)   // 786432 split weights
#define ARENA_F    ((size_t)403439616)

__device__ float g_arena[ARENA_F];

// weight sub-offsets (words) within OFF_W
#define WOFF_Q   0
#define WOFF_KV  65536
#define WOFF_P   196608
#define WOFF_W1  262144
#define WOFF_W2  524288

// ---------------------------------------------------------------------------
// Helpers (baseline PTX only: sm_80-era features, legal under .target sm_100)
// ---------------------------------------------------------------------------
__device__ __forceinline__ uint32_t s2u(const void* p) {
    uint32_t a;
    asm("{ .reg .u64 t; cvta.to.shared.u64 t, %1; cvt.u32.u64 %0, t; }" : "=r"(a) : "l"(p));
    return a;
}
__device__ __forceinline__ void cpa16(uint32_t saddr, const void* gptr) {
    asm volatile("cp.async.cg.shared.global [%0], [%1], 16;"
                 :: "r"(saddr), "l"(__cvta_generic_to_global(gptr)) : "memory");
}
__device__ __forceinline__ void cpa_commit() {
    asm volatile("cp.async.commit_group;" ::: "memory");
}
__device__ __forceinline__ uint32_t lds32(uint32_t a) {
    uint32_t v;
    asm volatile("ld.shared.b32 %0, [%1];" : "=r"(v) : "r"(a));
    return v;
}
__device__ __forceinline__ void mma16816(float& c0, float& c1, float& c2, float& c3,
                                         uint32_t a0, uint32_t a1, uint32_t a2, uint32_t a3,
                                         uint32_t b0, uint32_t b1) {
    asm volatile(
        "mma.sync.aligned.m16n8k16.row.col.f32.bf16.bf16.f32 "
        "{%0,%1,%2,%3}, {%4,%5,%6,%7}, {%8,%9}, {%0,%1,%2,%3};"
        : "+f"(c0), "+f"(c1), "+f"(c2), "+f"(c3)
        : "r"(a0), "r"(a1), "r"(a2), "r"(a3), "r"(b0), "r"(b1));
}
__device__ __forceinline__ float bf2f(uint32_t u16v) {
    return __uint_as_float(u16v << 16);
}
__device__ __forceinline__ void split2(float v, __nv_bfloat16& hi, __nv_bfloat16& lo) {
    hi = __float2bfloat16(v);
    lo = __float2bfloat16(v - __bfloat162float(hi));
}

// ---------------------------------------------------------------------------
// Weight split: fp32 -> hi/lo bf16 planes
// ---------------------------------------------------------------------------
__global__ void wsplit_kernel(const float* __restrict__ s, int n, int woff) {
    int i = blockIdx.x * 256 + threadIdx.x;
    if (i < n) {
        __nv_bfloat16* hi = (__nv_bfloat16*)((uint32_t*)g_arena + OFF_W + woff);
        __nv_bfloat16* lo = hi + n;
        __nv_bfloat16 h, l;
        split2(s[i], h, l);
        hi[i] = h; lo[i] = l;
    }
}

// ---------------------------------------------------------------------------
// LN1 + shift-roll + window partition -> qin / kvin split planes
// ---------------------------------------------------------------------------
__global__ __launch_bounds__(256)
void ln_window_kernel(const float* __restrict__ x,
                      const float* __restrict__ g1,
                      const float* __restrict__ b1)
{
    int token = blockIdx.x, tid = threadIdx.x;
    int w_idx = token >> 6, n = token & 63;
    int b = w_idx >> 10, win = w_idx & 1023;
    int wh = win >> 5, wwc = win & 31;
    int r = n >> 3, cw = n & 7;
    int sh = (wh * WS_ + r + SHIFT_) & (HHs - 1);
    int sw = (wwc * WS_ + cw + SHIFT_) & (WWs - 1);

    __shared__ float red[16];
    float gg = g1[tid], bcoef = b1[tid];
    int warp = tid >> 5, lane = tid & 31;
    uint32_t* au = (uint32_t*)g_arena;

    for (int dsel = 0; dsel < 2; dsel++) {
        size_t base = ((((size_t)b * 2 + dsel) * HHs + sh) * WWs + sw) * CCs;
        float v = x[base + tid];
        float s = v, sq = v * v;
        #pragma unroll
        for (int o = 16; o; o >>= 1) {
            s  += __shfl_xor_sync(0xffffffffu, s,  o);
            sq += __shfl_xor_sync(0xffffffffu, sq, o);
        }
        if (lane == 0) { red[warp] = s; red[8 + warp] = sq; }
        __syncthreads();
        if (tid < 32) {
            float a = (tid < 8) ? red[tid] : 0.f;
            float c = (tid < 8) ? red[8 + tid] : 0.f;
            #pragma unroll
            for (int o = 4; o; o >>= 1) {
                a += __shfl_xor_sync(0xffffffffu, a, o);
                c += __shfl_xor_sync(0xffffffffu, c, o);
            }
            if (tid == 0) { red[0] = a; red[1] = c; }
        }
        __syncthreads();
        float mean = red[0] * (1.f / CCs);
        float var  = red[1] * (1.f / CCs) - mean * mean;
        float rstd = rsqrtf(var + 1e-5f);
        float outv = (v - mean) * rstd * gg + bcoef;
        __nv_bfloat16 h, l;
        split2(outv, h, l);
        size_t e = (size_t)token * CCs + tid;
        __nv_bfloat16* hp = (__nv_bfloat16*)(au + (dsel == 0 ? OFF_QIN_S : OFF_KVIN_S));
        hp[e] = h;
        hp[(size_t)MTOK * CCs + e] = l;
        __syncthreads();
    }
}

// ---------------------------------------------------------------------------
// LN2: x1 fp32 -> xn2 split planes
// ---------------------------------------------------------------------------
__global__ __launch_bounds__(256)
void ln2_kernel(const float* __restrict__ g2, const float* __restrict__ b2)
{
    int token = blockIdx.x, tid = threadIdx.x;
    __shared__ float red[16];
    size_t base = (size_t)token * CCs;
    float v = g_arena[OFF_X1 + base + tid];
    float s = v, sq = v * v;
    #pragma unroll
    for (int o = 16; o; o >>= 1) {
        s  += __shfl_xor_sync(0xffffffffu, s,  o);
        sq += __shfl_xor_sync(0xffffffffu, sq, o);
    }
    int warp = tid >> 5, lane = tid & 31;
    if (lane == 0) { red[warp] = s; red[8 + warp] = sq; }
    __syncthreads();
    if (tid < 32) {
        float a = (tid < 8) ? red[tid] : 0.f;
        float c = (tid < 8) ? red[8 + tid] : 0.f;
        #pragma unroll
        for (int o = 4; o; o >>= 1) {
            a += __shfl_xor_sync(0xffffffffu, a, o);
            c += __shfl_xor_sync(0xffffffffu, c, o);
        }
        if (tid == 0) { red[0] = a; red[1] = c; }
    }
    __syncthreads();
    float mean = red[0] * (1.f / CCs);
    float var  = red[1] * (1.f / CCs) - mean * mean;
    float rstd = rsqrtf(var + 1e-5f);
    float outv = (v - mean) * rstd * g2[tid] + b2[tid];
    __nv_bfloat16 h, l;
    split2(outv, h, l);
    __nv_bfloat16* hp = (__nv_bfloat16*)((uint32_t*)g_arena + OFF_XN2_S);
    hp[base + tid] = h;
    hp[(size_t)MTOK * CCs + base + tid] = l;
}

// ---------------------------------------------------------------------------
// Split-bf16 warp-MMA GEMM (mma.sync m16n8k16, 3 passes: hh, hl, lh).
// CTA 128x128, BK=16, 8 warps (warp tile 64x32), cp.async double buffer.
// SMEM row stride 24 bf16 (48 B) -> conflict-free fragment LDS.
// Stage = 4 planes * 128 rows * 48 B = 24576 B; 2 stages = 49152 B dynamic
// (under the 48 KB default limit: NO cudaFuncSetAttribute needed).
// MODE 0: qin  -> q fp32  (acc+bias)*QSCALE
// MODE 1: kvin -> kv fp32
// MODE 2: attn -> x1 fp32 (+ qin + shortcut, scatter to image order)
// MODE 3: xn2  -> hid split (GELU)
// MODE 4: hid  -> dout fp32 (+x1)
// ---------------------------------------------------------------------------
#define PLANE_B 6144        // 128 rows * 48 B
#define STG_B   24576       // Ahi | Alo | Bhi | Blo
#define GSMEM   (2 * STG_B) // 49152

template<int MODE, int KDIM>
__global__ __launch_bounds__(256, 2)
void mma_gemm(const float* __restrict__ bias,
              const float* __restrict__ xsrc,
              float* __restrict__ dout)
{
    constexpr int NC = KDIM / 16;
    constexpr size_t E_A = (size_t)MTOK * KDIM;
    constexpr size_t E_B = (MODE == 0) ? 65536 : (MODE == 1) ? 131072 :
                           (MODE == 2) ? 65536 : 262144;
    constexpr size_t AOFF = (MODE == 0) ? OFF_QIN_S : (MODE == 1) ? OFF_KVIN_S :
                            (MODE == 2) ? OFF_ATTN_S : (MODE == 3) ? OFF_XN2_S : OFF_HID_S;
    constexpr size_t WO = OFF_W + ((MODE == 0) ? WOFF_Q : (MODE == 1) ? WOFF_KV :
                                   (MODE == 2) ? WOFF_P : (MODE == 3) ? WOFF_W1 : WOFF_W2);

    extern __shared__ char smem[];
    uint32_t sbase = s2u(smem);

    int tid = threadIdx.x;
    int wid = tid >> 5, lane = tid & 31;
    int g = lane >> 2, tg = lane & 3;
    int warpM = wid & 1, warpN = wid >> 1;
    int m0 = blockIdx.y * 128;
    int n0 = blockIdx.x * 128;

    uint32_t* au = (uint32_t*)g_arena;
    const __nv_bfloat16* Ahi = (const __nv_bfloat16*)(au + AOFF);
    const __nv_bfloat16* Alo = Ahi + E_A;
    const __nv_bfloat16* Bhi = (const __nv_bfloat16*)(au + WO);
    const __nv_bfloat16* Blo = Bhi + E_B;

    float acc[4][4][4];
    #pragma unroll
    for (int i = 0; i < 4; i++)
        #pragma unroll
        for (int j = 0; j < 4; j++)
            #pragma unroll
            for (int k = 0; k < 4; k++) acc[i][j][k] = 0.f;

    // 256 threads: idx 0..255 -> row = idx>>1 (0..127), k8 = (idx&1)*8
    auto load_chunk = [&](int s, int kc0) {
        uint32_t sb = sbase + s * STG_B;
        int row = tid >> 1, k8 = (tid & 1) * 8;
        uint32_t so = sb + row * 48 + k8 * 2;
        size_t ga = (size_t)(m0 + row) * KDIM + kc0 + k8;
        size_t gb = (size_t)(n0 + row) * KDIM + kc0 + k8;
        cpa16(so,               Ahi + ga);
        cpa16(so + PLANE_B,     Alo + ga);
        cpa16(so + 2 * PLANE_B, Bhi + gb);
        cpa16(so + 3 * PLANE_B, Blo + gb);
        cpa_commit();
    };

    auto compute = [&](int s) {
        uint32_t stg = sbase + s * STG_B;
        int ko = tg * 2;
        #pragma unroll
        for (int p = 0; p < 3; p++) {
            uint32_t aB = stg + (p == 2 ? PLANE_B : 0);
            uint32_t bB = stg + 2 * PLANE_B + (p == 1 ? PLANE_B : 0);
            uint32_t a[4][4], b[4][2];
            #pragma unroll
            for (int mt = 0; mt < 4; mt++) {
                int rb = warpM * 64 + mt * 16 + g;
                a[mt][0] = lds32(aB + (rb * 24 + ko) * 2);
                a[mt][1] = lds32(aB + ((rb + 8) * 24 + ko) * 2);
                a[mt][2] = lds32(aB + (rb * 24 + ko + 8) * 2);
                a[mt][3] = lds32(aB + ((rb + 8) * 24 + ko + 8) * 2);
            }
            #pragma unroll
            for (int nt = 0; nt < 4; nt++) {
                int rn = warpN * 32 + nt * 8 + g;
                b[nt][0] = lds32(bB + (rn * 24 + ko) * 2);
                b[nt][1] = lds32(bB + (rn * 24 + ko + 8) * 2);
            }
            #pragma unroll
            for (int mt = 0; mt < 4; mt++)
                #pragma unroll
                for (int nt = 0; nt < 4; nt++)
                    mma16816(acc[mt][nt][0], acc[mt][nt][1], acc[mt][nt][2], acc[mt][nt][3],
                             a[mt][0], a[mt][1], a[mt][2], a[mt][3],
                             b[nt][0], b[nt][1]);
        }
    };

    load_chunk(0, 0);
    for (int c = 0; c < NC; c++) {
        if (c + 1 < NC) {
            load_chunk((c + 1) & 1, (c + 1) * 16);
            asm volatile("cp.async.wait_group 1;" ::: "memory");
        } else {
            asm volatile("cp.async.wait_group 0;" ::: "memory");
        }
        __syncthreads();
        compute(c & 1);
        __syncthreads();
    }

    // ------------------------------- epilogue -------------------------------
    int tg2 = tg * 2;
    int coln[4];
    float2 bb[4];
    #pragma unroll
    for (int nt = 0; nt < 4; nt++) {
        coln[nt] = n0 + warpN * 32 + nt * 8 + tg2;
        bb[nt] = *(const float2*)(bias + coln[nt]);
    }

    #pragma unroll
    for (int mt = 0; mt < 4; mt++) {
        #pragma unroll
        for (int rr = 0; rr < 2; rr++) {
            int row = m0 + warpM * 64 + mt * 16 + g + rr * 8;

            size_t img = 0, ximg = 0;
            if (MODE == 2) {
                int w_idx = row >> 6, nn = row & 63;
                int b = w_idx >> 10, win = w_idx & 1023;
                int wh = win >> 5, wwc = win & 31;
                int r = nn >> 3, cw = nn & 7;
                int hi_ = (wh * WS_ + r + SHIFT_) & (HHs - 1);
                int wi_ = (wwc * WS_ + cw + SHIFT_) & (WWs - 1);
                img  = (((size_t)b * HHs + hi_) * WWs + wi_) * CCs;
                ximg = ((((size_t)b * 2) * HHs + hi_) * WWs + wi_) * CCs;
            }

            #pragma unroll
            for (int nt = 0; nt < 4; nt++) {
                int col = coln[nt];
                float v0 = acc[mt][nt][rr * 2 + 0] + bb[nt].x;
                float v1 = acc[mt][nt][rr * 2 + 1] + bb[nt].y;

                if (MODE == 0) {
                    *(float2*)(g_arena + OFF_Q + (size_t)row * 256 + col) =
                        make_float2(v0 * QSCALE, v1 * QSCALE);
                } else if (MODE == 1) {
                    *(float2*)(g_arena + OFF_KV + (size_t)row * 512 + col) =
                        make_float2(v0, v1);
                } else if (MODE == 2) {
                    size_t widx = (size_t)row * 128 + (col >> 1);
                    uint32_t hq = au[OFF_QIN_S + widx];
                    uint32_t lq = au[OFF_QIN_S + 16777216 + widx];
                    float2 sc = *(const float2*)(xsrc + ximg + col);
                    v0 += bf2f(hq & 0xFFFFu) + bf2f(lq & 0xFFFFu) + sc.x;
                    v1 += bf2f(hq >> 16)     + bf2f(lq >> 16)     + sc.y;
                    *(float2*)(g_arena + OFF_X1 + img + col) = make_float2(v0, v1);
                } else if (MODE == 3) {
                    float g0 = v0 * normcdff(v0);
                    float g1 = v1 * normcdff(v1);
                    __nv_bfloat16 h0, l0, h1, l1;
                    split2(g0, h0, l0); split2(g1, h1, l1);
                    size_t widx = (size_t)row * 512 + (col >> 1);
                    au[OFF_HID_S + widx] =
                        (uint32_t)__bfloat16_as_ushort(h0) |
                        ((uint32_t)__bfloat16_as_ushort(h1) << 16);
                    au[OFF_HID_S + 67108864 + widx] =
                        (uint32_t)__bfloat16_as_ushort(l0) |
                        ((uint32_t)__bfloat16_as_ushort(l1) << 16);
                } else { // MODE 4
                    float2 x1v = *(const float2*)(g_arena + OFF_X1 + (size_t)row * 256 + col);
                    *(float2*)(dout + (size_t)row * 256 + col) =
                        make_float2(v0 + x1v.x, v1 + x1v.y);
                }
            }
        }
    }
}

// ---------------------------------------------------------------------------
// Windowed attention. One block per (window, head). Reads q/kv fp32,
// writes attn split planes.
// ---------------------------------------------------------------------------
__global__ __launch_bounds__(64)
void attn_kernel(const float* __restrict__ mask, const float* __restrict__ btab)
{
    int w_idx = blockIdx.x, hh = blockIdx.y, t = threadIdx.x;
    __shared__ float ksh[64 * 36];
    __shared__ float vsh[64 * 36];
    __shared__ float sbias[225];

    for (int i = t; i < 225; i += 64) sbias[i] = btab[i * 8 + hh];

    const float* kvp = g_arena + OFF_KV + ((size_t)w_idx * 64 + t) * 512 + hh * 32;
    #pragma unroll
    for (int q4 = 0; q4 < 8; q4++) {
        *(float4*)&ksh[t * 36 + q4 * 4] = *(const float4*)(kvp + q4 * 4);
        *(float4*)&vsh[t * 36 + q4 * 4] = *(const float4*)(kvp + 256 + q4 * 4);
    }

    float q[32];
    const float* qp = g_arena + OFF_Q + ((size_t)w_idx * 64 + t) * 256 + hh * 32;
    #pragma unroll
    for (int q4 = 0; q4 < 8; q4++) {
        float4 qq = *(const float4*)(qp + q4 * 4);
        q[q4*4+0] = qq.x; q[q4*4+1] = qq.y; q[q4*4+2] = qq.z; q[q4*4+3] = qq.w;
    }
    __syncthreads();

    int r1 = t >> 3, c1 = t & 7;
    int win = w_idx & 1023;
    const float* mrow = mask + ((size_t)win * 64 + t) * 64;

    float s[64];
    #pragma unroll
    for (int m = 0; m < 64; m++) {
        float acc = 0.f;
        #pragma unroll
        for (int d4 = 0; d4 < 8; d4++) {
            float4 kk = *(const float4*)&ksh[m * 36 + d4 * 4];
            acc += q[d4*4+0]*kk.x + q[d4*4+1]*kk.y + q[d4*4+2]*kk.z + q[d4*4+3]*kk.w;
        }
        int r2 = m >> 3, c2 = m & 7;
        s[m] = acc + sbias[(r1 - r2 + 7) * 15 + (c1 - c2 + 7)] + mrow[m];
    }

    float mx = -1e30f;
    #pragma unroll
    for (int m = 0; m < 64; m++) mx = fmaxf(mx, s[m]);
    float sum = 0.f;
    #pragma unroll
    for (int m = 0; m < 64; m++) { s[m] = __expf(s[m] - mx); sum += s[m]; }
    float inv = 1.f / sum;

    float o[32];
    #pragma unroll
    for (int j = 0; j < 32; j++) o[j] = 0.f;
    #pragma unroll
    for (int m = 0; m < 64; m++) {
        float p = s[m];
        #pragma unroll
        for (int d4 = 0; d4 < 8; d4++) {
            float4 vv = *(const float4*)&vsh[m * 36 + d4 * 4];
            o[d4*4+0] += p * vv.x; o[d4*4+1] += p * vv.y;
            o[d4*4+2] += p * vv.z; o[d4*4+3] += p * vv.w;
        }
    }

    // split-pack output (hi/lo planes)
    uint32_t* au = (uint32_t*)g_arena;
    size_t base = ((size_t)w_idx * 64 + t) * 256 + hh * 32;
    #pragma unroll
    for (int j = 0; j < 16; j++) {
        float a = o[2*j] * inv, b = o[2*j+1] * inv;
        __nv_bfloat16 ha, la, hb, lb;
        split2(a, ha, la); split2(b, hb, lb);
        size_t widx = (base >> 1) + j;
        au[OFF_ATTN_S + widx] =
            (uint32_t)__bfloat16_as_ushort(ha) | ((uint32_t)__bfloat16_as_ushort(hb) << 16);
        au[OFF_ATTN_S + 16777216 + widx] =
            (uint32_t)__bfloat16_as_ushort(la) | ((uint32_t)__bfloat16_as_ushort(lb) << 16);
    }
}

// ---------------------------------------------------------------------------
// Launch — pure kernel launches only (no attribute calls, <=48KB dyn smem).
// ---------------------------------------------------------------------------
extern "C" void kernel_launch(void* const* d_in, const int* in_sizes, int n_in,
                              void* d_out, int out_size)
{
    const float* x     = (const float*)d_in[0];
    const float* maskm = (const float*)d_in[1];
    const float* g1    = (const float*)d_in[2];
    const float* b1    = (const float*)d_in[3];
    const float* qw    = (const float*)d_in[4];
    const float* qb    = (const float*)d_in[5];
    const float* kvw   = (const float*)d_in[6];
    const float* kvb   = (const float*)d_in[7];
    const float* pw    = (const float*)d_in[8];
    const float* pb    = (const float*)d_in[9];
    const float* btab  = (const float*)d_in[10];
    const float* g2    = (const float*)d_in[11];
    const float* b2    = (const float*)d_in[12];
    const float* w1    = (const float*)d_in[13];
    const float* bi1   = (const float*)d_in[14];
    const float* w2    = (const float*)d_in[15];
    const float* bi2   = (const float*)d_in[16];
    float* out = (float*)d_out;

    // 0) split weights into bf16 hi/lo planes
    wsplit_kernel<<<256,  256>>>(qw,  65536,  WOFF_Q);
    wsplit_kernel<<<512,  256>>>(kvw, 131072, WOFF_KV);
    wsplit_kernel<<<256,  256>>>(pw,  65536,  WOFF_P);
    wsplit_kernel<<<1024, 256>>>(w1,  262144, WOFF_W1);
    wsplit_kernel<<<1024, 256>>>(w2,  262144, WOFF_W2);

    // 1) LN1 + shift + window partition
    ln_window_kernel<<<MTOK, 256>>>(x, g1, b1);

    // 2) q projection (N=256)
    mma_gemm<0,256><<<dim3(2, 1024), 256, GSMEM>>>(qb, nullptr, nullptr);

    // 3) kv projection (N=512)
    mma_gemm<1,256><<<dim3(4, 1024), 256, GSMEM>>>(kvb, nullptr, nullptr);

    // 4) windowed attention
    attn_kernel<<<dim3(2048, 8), 64>>>(maskm, btab);

    // 5) output projection + residuals + scatter -> x1
    mma_gemm<2,256><<<dim3(2, 1024), 256, GSMEM>>>(pb, x, nullptr);

    // 6) LN2
    ln2_kernel<<<MTOK, 256>>>(g2, b2);

    // 7) MLP up + GELU (N=1024)
    mma_gemm<3,256><<<dim3(8, 1024), 256, GSMEM>>>(bi1, nullptr, nullptr);

    // 8) MLP down + residual -> out (K=1024)
    mma_gemm<4,1024><<<dim3(2, 1024), 256, GSMEM>>>(bi2, nullptr, out);
}

// round 9
// speedup vs baseline: 2.0987x; 1.0258x over previous
#include <cuda_runtime.h>
#include <cuda_bf16.h>
#include <math.h>
#include <stdint.h>

// ---------------------------------------------------------------------------
// Problem constants
// ---------------------------------------------------------------------------
#define HHs     256
#define WWs     256
#define CCs     256
#define WS_     8
#define SHIFT_  4
#define MTOK    131072
#define QSCALE  0.17677669529663689f  // 1/sqrt(32)

// ---------------------------------------------------------------------------
// Arena (u32 words). Split tensors = two bf16 planes: hi[E], lo[E].
// ---------------------------------------------------------------------------
#define OFF_QIN_S  ((size_t)0)           // 33.5M  split (window order)
#define OFF_KVIN_S ((size_t)33554432)    // 33.5M  split
#define OFF_Q      ((size_t)67108864)    // 33.5M  fp32
#define OFF_KV     ((size_t)100663296)   // 67.1M  fp32
#define OFF_ATTN_S ((size_t)167772160)   // 33.5M  split
#define OFF_X1     ((size_t)201326592)   // 33.5M  fp32 (image order)
#define OFF_XN2_S  ((size_t)234881024)   // 33.5M  split
#define OFF_HID_S  ((size_t)268435456)   // 134.2M split
#define OFF_W      ((size_t)402653184)   // 786432 split weights
#define ARENA_F    ((size_t)403439616)

__device__ float g_arena[ARENA_F];

// weight sub-offsets (words) within OFF_W
#define WOFF_Q   0
#define WOFF_KV  65536
#define WOFF_P   196608
#define WOFF_W1  262144
#define WOFF_W2  524288

// ---------------------------------------------------------------------------
// Helpers (baseline PTX only: sm_80-era features, legal under .target sm_100)
// ---------------------------------------------------------------------------
__device__ __forceinline__ uint32_t s2u(const void* p) {
    uint32_t a;
    asm("{ .reg .u64 t; cvta.to.shared.u64 t, %1; cvt.u32.u64 %0, t; }" : "=r"(a) : "l"(p));
    return a;
}
__device__ __forceinline__ void cpa16(uint32_t saddr, const void* gptr) {
    asm volatile("cp.async.cg.shared.global [%0], [%1], 16;"
                 :: "r"(saddr), "l"(__cvta_generic_to_global(gptr)) : "memory");
}
__device__ __forceinline__ void cpa_commit() {
    asm volatile("cp.async.commit_group;" ::: "memory");
}
__device__ __forceinline__ void ldmx4(uint32_t* r, uint32_t addr) {
    asm volatile("ldmatrix.sync.aligned.m8n8.x4.shared.b16 {%0,%1,%2,%3}, [%4];"
                 : "=r"(r[0]), "=r"(r[1]), "=r"(r[2]), "=r"(r[3]) : "r"(addr));
}
__device__ __forceinline__ void mma16816(float& c0, float& c1, float& c2, float& c3,
                                         uint32_t a0, uint32_t a1, uint32_t a2, uint32_t a3,
                                         uint32_t b0, uint32_t b1) {
    asm volatile(
        "mma.sync.aligned.m16n8k16.row.col.f32.bf16.bf16.f32 "
        "{%0,%1,%2,%3}, {%4,%5,%6,%7}, {%8,%9}, {%0,%1,%2,%3};"
        : "+f"(c0), "+f"(c1), "+f"(c2), "+f"(c3)
        : "r"(a0), "r"(a1), "r"(a2), "r"(a3), "r"(b0), "r"(b1));
}
__device__ __forceinline__ float bf2f(uint32_t u16v) {
    return __uint_as_float(u16v << 16);
}
__device__ __forceinline__ void split2(float v, __nv_bfloat16& hi, __nv_bfloat16& lo) {
    hi = __float2bfloat16(v);
    lo = __float2bfloat16(v - __bfloat162float(hi));
}

// ---------------------------------------------------------------------------
// Weight split: all 5 weights in ONE launch (keeps launch #5 = a GEMM so the
// fixed `-s 5 -c 1` ncu capture profiles something useful).
// Segments: q[65536] kv[131072] p[65536] w1[262144] w2[262144] = 786432 elems.
// ---------------------------------------------------------------------------
__global__ void wsplit_all(const float* __restrict__ qw, const float* __restrict__ kvw,
                           const float* __restrict__ pw, const float* __restrict__ w1,
                           const float* __restrict__ w2) {
    int i = blockIdx.x * 256 + threadIdx.x;   // 0..786431
    const float* src; int n, woff, j = i;
    if (j < 65536)        { src = qw;  n = 65536;  woff = WOFF_Q; }
    else if ((j -= 65536) < 131072) { src = kvw; n = 131072; woff = WOFF_KV; }
    else if ((j -= 131072) < 65536) { src = pw;  n = 65536;  woff = WOFF_P; }
    else if ((j -= 65536) < 262144) { src = w1;  n = 262144; woff = WOFF_W1; }
    else { j -= 262144;               src = w2;  n = 262144; woff = WOFF_W2; }
    __nv_bfloat16* hi = (__nv_bfloat16*)((uint32_t*)g_arena + OFF_W + woff);
    __nv_bfloat16* lo = hi + n;
    __nv_bfloat16 h, l;
    split2(src[j], h, l);
    hi[j] = h; lo[j] = l;
}

// ---------------------------------------------------------------------------
// LN1 + shift-roll + window partition -> qin / kvin split planes
// ---------------------------------------------------------------------------
__global__ __launch_bounds__(256)
void ln_window_kernel(const float* __restrict__ x,
                      const float* __restrict__ g1,
                      const float* __restrict__ b1)
{
    int token = blockIdx.x, tid = threadIdx.x;
    int w_idx = token >> 6, n = token & 63;
    int b = w_idx >> 10, win = w_idx & 1023;
    int wh = win >> 5, wwc = win & 31;
    int r = n >> 3, cw = n & 7;
    int sh = (wh * WS_ + r + SHIFT_) & (HHs - 1);
    int sw = (wwc * WS_ + cw + SHIFT_) & (WWs - 1);

    __shared__ float red[16];
    float gg = g1[tid], bcoef = b1[tid];
    int warp = tid >> 5, lane = tid & 31;
    uint32_t* au = (uint32_t*)g_arena;

    for (int dsel = 0; dsel < 2; dsel++) {
        size_t base = ((((size_t)b * 2 + dsel) * HHs + sh) * WWs + sw) * CCs;
        float v = x[base + tid];
        float s = v, sq = v * v;
        #pragma unroll
        for (int o = 16; o; o >>= 1) {
            s  += __shfl_xor_sync(0xffffffffu, s,  o);
            sq += __shfl_xor_sync(0xffffffffu, sq, o);
        }
        if (lane == 0) { red[warp] = s; red[8 + warp] = sq; }
        __syncthreads();
        if (tid < 32) {
            float a = (tid < 8) ? red[tid] : 0.f;
            float c = (tid < 8) ? red[8 + tid] : 0.f;
            #pragma unroll
            for (int o = 4; o; o >>= 1) {
                a += __shfl_xor_sync(0xffffffffu, a, o);
                c += __shfl_xor_sync(0xffffffffu, c, o);
            }
            if (tid == 0) { red[0] = a; red[1] = c; }
        }
        __syncthreads();
        float mean = red[0] * (1.f / CCs);
        float var  = red[1] * (1.f / CCs) - mean * mean;
        float rstd = rsqrtf(var + 1e-5f);
        float outv = (v - mean) * rstd * gg + bcoef;
        __nv_bfloat16 h, l;
        split2(outv, h, l);
        size_t e = (size_t)token * CCs + tid;
        __nv_bfloat16* hp = (__nv_bfloat16*)(au + (dsel == 0 ? OFF_QIN_S : OFF_KVIN_S));
        hp[e] = h;
        hp[(size_t)MTOK * CCs + e] = l;
        __syncthreads();
    }
}

// ---------------------------------------------------------------------------
// LN2: x1 fp32 -> xn2 split planes
// ---------------------------------------------------------------------------
__global__ __launch_bounds__(256)
void ln2_kernel(const float* __restrict__ g2, const float* __restrict__ b2)
{
    int token = blockIdx.x, tid = threadIdx.x;
    __shared__ float red[16];
    size_t base = (size_t)token * CCs;
    float v = g_arena[OFF_X1 + base + tid];
    float s = v, sq = v * v;
    #pragma unroll
    for (int o = 16; o; o >>= 1) {
        s  += __shfl_xor_sync(0xffffffffu, s,  o);
        sq += __shfl_xor_sync(0xffffffffu, sq, o);
    }
    int warp = tid >> 5, lane = tid & 31;
    if (lane == 0) { red[warp] = s; red[8 + warp] = sq; }
    __syncthreads();
    if (tid < 32) {
        float a = (tid < 8) ? red[tid] : 0.f;
        float c = (tid < 8) ? red[8 + tid] : 0.f;
        #pragma unroll
        for (int o = 4; o; o >>= 1) {
            a += __shfl_xor_sync(0xffffffffu, a, o);
            c += __shfl_xor_sync(0xffffffffu, c, o);
        }
        if (tid == 0) { red[0] = a; red[1] = c; }
    }
    __syncthreads();
    float mean = red[0] * (1.f / CCs);
    float var  = red[1] * (1.f / CCs) - mean * mean;
    float rstd = rsqrtf(var + 1e-5f);
    float outv = (v - mean) * rstd * g2[tid] + b2[tid];
    __nv_bfloat16 h, l;
    split2(outv, h, l);
    __nv_bfloat16* hp = (__nv_bfloat16*)((uint32_t*)g_arena + OFF_XN2_S);
    hp[base + tid] = h;
    hp[(size_t)MTOK * CCs + base + tid] = l;
}

// ---------------------------------------------------------------------------
// Split-bf16 warp-MMA GEMM (mma.sync m16n8k16, 3 passes: hh, hl, lh).
// CTA 128x128, BK=16, 8 warps (warp tile 64x32), cp.async double buffer.
// Fragments loaded via ldmatrix.m8n8.x4 (4x fewer shared-load instructions).
// SMEM row stride 24 bf16 (48 B): conflict-free for both cp.async stores and
// ldmatrix phases (48*row mod 128 permutes all eight 16B slots).
// ---------------------------------------------------------------------------
#define PLANE_B 6144        // 128 rows * 48 B
#define STG_B   24576       // Ahi | Alo | Bhi | Blo
#define GSMEM   (2 * STG_B) // 49152 (under default 48KB limit, no opt-in)

template<int MODE, int KDIM>
__global__ __launch_bounds__(256, 2)
void mma_gemm(const float* __restrict__ bias,
              const float* __restrict__ xsrc,
              float* __restrict__ dout)
{
    constexpr int NC = KDIM / 16;
    constexpr size_t E_A = (size_t)MTOK * KDIM;
    constexpr size_t E_B = (MODE == 0) ? 65536 : (MODE == 1) ? 131072 :
                           (MODE == 2) ? 65536 : 262144;
    constexpr size_t AOFF = (MODE == 0) ? OFF_QIN_S : (MODE == 1) ? OFF_KVIN_S :
                            (MODE == 2) ? OFF_ATTN_S : (MODE == 3) ? OFF_XN2_S : OFF_HID_S;
    constexpr size_t WO = OFF_W + ((MODE == 0) ? WOFF_Q : (MODE == 1) ? WOFF_KV :
                                   (MODE == 2) ? WOFF_P : (MODE == 3) ? WOFF_W1 : WOFF_W2);

    extern __shared__ char smem[];
    uint32_t sbase = s2u(smem);

    int tid = threadIdx.x;
    int wid = tid >> 5, lane = tid & 31;
    int g = lane >> 2, tg = lane & 3;
    int warpM = wid & 1, warpN = wid >> 1;
    int m0 = blockIdx.y * 128;
    int n0 = blockIdx.x * 128;

    uint32_t* au = (uint32_t*)g_arena;
    const __nv_bfloat16* Ahi = (const __nv_bfloat16*)(au + AOFF);
    const __nv_bfloat16* Alo = Ahi + E_A;
    const __nv_bfloat16* Bhi = (const __nv_bfloat16*)(au + WO);
    const __nv_bfloat16* Blo = Bhi + E_B;

    float acc[4][4][4];
    #pragma unroll
    for (int i = 0; i < 4; i++)
        #pragma unroll
        for (int j = 0; j < 4; j++)
            #pragma unroll
            for (int k = 0; k < 4; k++) acc[i][j][k] = 0.f;

    // ldmatrix per-lane source rows/offsets (within-tile; constant per thread)
    int l7 = lane & 7;
    int a_row = warpM * 64 + l7 + ((lane >> 3) & 1) * 8;   // + mt*16
    int a_kof = (lane >> 4) * 8;
    int b_row = warpN * 32 + l7 + ((lane >> 4) & 1) * 8;   // + pair*16
    int b_kof = ((lane >> 3) & 1) * 8;

    auto load_chunk = [&](int s, int kc0) {
        uint32_t sb = sbase + s * STG_B;
        int row = tid >> 1, k8 = (tid & 1) * 8;
        uint32_t so = sb + row * 48 + k8 * 2;
        size_t ga = (size_t)(m0 + row) * KDIM + kc0 + k8;
        size_t gb = (size_t)(n0 + row) * KDIM + kc0 + k8;
        cpa16(so,               Ahi + ga);
        cpa16(so + PLANE_B,     Alo + ga);
        cpa16(so + 2 * PLANE_B, Bhi + gb);
        cpa16(so + 3 * PLANE_B, Blo + gb);
        cpa_commit();
    };

    auto compute = [&](int s) {
        uint32_t stg = sbase + s * STG_B;
        #pragma unroll
        for (int p = 0; p < 3; p++) {
            uint32_t aB = stg + (p == 2 ? PLANE_B : 0);
            uint32_t bB = stg + 2 * PLANE_B + (p == 1 ? PLANE_B : 0);
            uint32_t a[4][4], b[4][2];
            #pragma unroll
            for (int mt = 0; mt < 4; mt++)
                ldmx4(a[mt], aB + ((a_row + mt * 16) * 24 + a_kof) * 2);
            // pair 0 -> b[0], b[1];  pair 1 -> b[2], b[3]
            {
                uint32_t t4[4];
                ldmx4(t4, bB + (b_row * 24 + b_kof) * 2);
                b[0][0] = t4[0]; b[0][1] = t4[1]; b[1][0] = t4[2]; b[1][1] = t4[3];
                ldmx4(t4, bB + ((b_row + 16) * 24 + b_kof) * 2);
                b[2][0] = t4[0]; b[2][1] = t4[1]; b[3][0] = t4[2]; b[3][1] = t4[3];
            }
            #pragma unroll
            for (int mt = 0; mt < 4; mt++)
                #pragma unroll
                for (int nt = 0; nt < 4; nt++)
                    mma16816(acc[mt][nt][0], acc[mt][nt][1], acc[mt][nt][2], acc[mt][nt][3],
                             a[mt][0], a[mt][1], a[mt][2], a[mt][3],
                             b[nt][0], b[nt][1]);
        }
    };

    load_chunk(0, 0);
    for (int c = 0; c < NC; c++) {
        if (c + 1 < NC) {
            load_chunk((c + 1) & 1, (c + 1) * 16);
            asm volatile("cp.async.wait_group 1;" ::: "memory");
        } else {
            asm volatile("cp.async.wait_group 0;" ::: "memory");
        }
        __syncthreads();
        compute(c & 1);
        __syncthreads();
    }

    // ------------------------------- epilogue -------------------------------
    int tg2 = tg * 2;
    int coln[4];
    float2 bb[4];
    #pragma unroll
    for (int nt = 0; nt < 4; nt++) {
        coln[nt] = n0 + warpN * 32 + nt * 8 + tg2;
        bb[nt] = *(const float2*)(bias + coln[nt]);
    }

    #pragma unroll
    for (int mt = 0; mt < 4; mt++) {
        #pragma unroll
        for (int rr = 0; rr < 2; rr++) {
            int row = m0 + warpM * 64 + mt * 16 + g + rr * 8;

            size_t img = 0, ximg = 0;
            if (MODE == 2) {
                int w_idx = row >> 6, nn = row & 63;
                int b = w_idx >> 10, win = w_idx & 1023;
                int wh = win >> 5, wwc = win & 31;
                int r = nn >> 3, cw = nn & 7;
                int hi_ = (wh * WS_ + r + SHIFT_) & (HHs - 1);
                int wi_ = (wwc * WS_ + cw + SHIFT_) & (WWs - 1);
                img  = (((size_t)b * HHs + hi_) * WWs + wi_) * CCs;
                ximg = ((((size_t)b * 2) * HHs + hi_) * WWs + wi_) * CCs;
            }

            #pragma unroll
            for (int nt = 0; nt < 4; nt++) {
                int col = coln[nt];
                float v0 = acc[mt][nt][rr * 2 + 0] + bb[nt].x;
                float v1 = acc[mt][nt][rr * 2 + 1] + bb[nt].y;

                if (MODE == 0) {
                    *(float2*)(g_arena + OFF_Q + (size_t)row * 256 + col) =
                        make_float2(v0 * QSCALE, v1 * QSCALE);
                } else if (MODE == 1) {
                    *(float2*)(g_arena + OFF_KV + (size_t)row * 512 + col) =
                        make_float2(v0, v1);
                } else if (MODE == 2) {
                    size_t widx = (size_t)row * 128 + (col >> 1);
                    uint32_t hq = au[OFF_QIN_S + widx];
                    uint32_t lq = au[OFF_QIN_S + 16777216 + widx];
                    float2 sc = *(const float2*)(xsrc + ximg + col);
                    v0 += bf2f(hq & 0xFFFFu) + bf2f(lq & 0xFFFFu) + sc.x;
                    v1 += bf2f(hq >> 16)     + bf2f(lq >> 16)     + sc.y;
                    *(float2*)(g_arena + OFF_X1 + img + col) = make_float2(v0, v1);
                } else if (MODE == 3) {
                    float g0 = v0 * normcdff(v0);
                    float g1 = v1 * normcdff(v1);
                    __nv_bfloat16 h0, l0, h1, l1;
                    split2(g0, h0, l0); split2(g1, h1, l1);
                    size_t widx = (size_t)row * 512 + (col >> 1);
                    au[OFF_HID_S + widx] =
                        (uint32_t)__bfloat16_as_ushort(h0) |
                        ((uint32_t)__bfloat16_as_ushort(h1) << 16);
                    au[OFF_HID_S + 67108864 + widx] =
                        (uint32_t)__bfloat16_as_ushort(l0) |
                        ((uint32_t)__bfloat16_as_ushort(l1) << 16);
                } else { // MODE 4
                    float2 x1v = *(const float2*)(g_arena + OFF_X1 + (size_t)row * 256 + col);
                    *(float2*)(dout + (size_t)row * 256 + col) =
                        make_float2(v0 + x1v.x, v1 + x1v.y);
                }
            }
        }
    }
}

// ---------------------------------------------------------------------------
// Windowed attention. One block per (window, head). Reads q/kv fp32,
// writes attn split planes.
// ---------------------------------------------------------------------------
__global__ __launch_bounds__(64)
void attn_kernel(const float* __restrict__ mask, const float* __restrict__ btab)
{
    int w_idx = blockIdx.x, hh = blockIdx.y, t = threadIdx.x;
    __shared__ float ksh[64 * 36];
    __shared__ float vsh[64 * 36];
    __shared__ float sbias[225];

    for (int i = t; i < 225; i += 64) sbias[i] = btab[i * 8 + hh];

    const float* kvp = g_arena + OFF_KV + ((size_t)w_idx * 64 + t) * 512 + hh * 32;
    #pragma unroll
    for (int q4 = 0; q4 < 8; q4++) {
        *(float4*)&ksh[t * 36 + q4 * 4] = *(const float4*)(kvp + q4 * 4);
        *(float4*)&vsh[t * 36 + q4 * 4] = *(const float4*)(kvp + 256 + q4 * 4);
    }

    float q[32];
    const float* qp = g_arena + OFF_Q + ((size_t)w_idx * 64 + t) * 256 + hh * 32;
    #pragma unroll
    for (int q4 = 0; q4 < 8; q4++) {
        float4 qq = *(const float4*)(qp + q4 * 4);
        q[q4*4+0] = qq.x; q[q4*4+1] = qq.y; q[q4*4+2] = qq.z; q[q4*4+3] = qq.w;
    }
    __syncthreads();

    int r1 = t >> 3, c1 = t & 7;
    int win = w_idx & 1023;
    const float* mrow = mask + ((size_t)win * 64 + t) * 64;

    float s[64];
    #pragma unroll
    for (int m = 0; m < 64; m++) {
        float acc = 0.f;
        #pragma unroll
        for (int d4 = 0; d4 < 8; d4++) {
            float4 kk = *(const float4*)&ksh[m * 36 + d4 * 4];
            acc += q[d4*4+0]*kk.x + q[d4*4+1]*kk.y + q[d4*4+2]*kk.z + q[d4*4+3]*kk.w;
        }
        int r2 = m >> 3, c2 = m & 7;
        s[m] = acc + sbias[(r1 - r2 + 7) * 15 + (c1 - c2 + 7)] + mrow[m];
    }

    float mx = -1e30f;
    #pragma unroll
    for (int m = 0; m < 64; m++) mx = fmaxf(mx, s[m]);
    float sum = 0.f;
    #pragma unroll
    for (int m = 0; m < 64; m++) { s[m] = __expf(s[m] - mx); sum += s[m]; }
    float inv = 1.f / sum;

    float o[32];
    #pragma unroll
    for (int j = 0; j < 32; j++) o[j] = 0.f;
    #pragma unroll
    for (int m = 0; m < 64; m++) {
        float p = s[m];
        #pragma unroll
        for (int d4 = 0; d4 < 8; d4++) {
            float4 vv = *(const float4*)&vsh[m * 36 + d4 * 4];
            o[d4*4+0] += p * vv.x; o[d4*4+1] += p * vv.y;
            o[d4*4+2] += p * vv.z; o[d4*4+3] += p * vv.w;
        }
    }

    // split-pack output (hi/lo planes)
    uint32_t* au = (uint32_t*)g_arena;
    size_t base = ((size_t)w_idx * 64 + t) * 256 + hh * 32;
    #pragma unroll
    for (int j = 0; j < 16; j++) {
        float a = o[2*j] * inv, b = o[2*j+1] * inv;
        __nv_bfloat16 ha, la, hb, lb;
        split2(a, ha, la); split2(b, hb, lb);
        size_t widx = (base >> 1) + j;
        au[OFF_ATTN_S + widx] =
            (uint32_t)__bfloat16_as_ushort(ha) | ((uint32_t)__bfloat16_as_ushort(hb) << 16);
        au[OFF_ATTN_S + 16777216 + widx] =
            (uint32_t)__bfloat16_as_ushort(la) | ((uint32_t)__bfloat16_as_ushort(lb) << 16);
    }
}

// ---------------------------------------------------------------------------
// Launch — pure kernel launches only (no attribute calls, <=48KB dyn smem).
// Launch order puts mma_gemm<2> at index 5 for the fixed ncu -s 5 capture.
// ---------------------------------------------------------------------------
extern "C" void kernel_launch(void* const* d_in, const int* in_sizes, int n_in,
                              void* d_out, int out_size)
{
    const float* x     = (const float*)d_in[0];
    const float* maskm = (const float*)d_in[1];
    const float* g1    = (const float*)d_in[2];
    const float* b1    = (const float*)d_in[3];
    const float* qw    = (const float*)d_in[4];
    const float* qb    = (const float*)d_in[5];
    const float* kvw   = (const float*)d_in[6];
    const float* kvb   = (const float*)d_in[7];
    const float* pw    = (const float*)d_in[8];
    const float* pb    = (const float*)d_in[9];
    const float* btab  = (const float*)d_in[10];
    const float* g2    = (const float*)d_in[11];
    const float* b2    = (const float*)d_in[12];
    const float* w1    = (const float*)d_in[13];
    const float* bi1   = (const float*)d_in[14];
    const float* w2    = (const float*)d_in[15];
    const float* bi2   = (const float*)d_in[16];
    float* out = (float*)d_out;

    // 0) split all weights (single launch)
    wsplit_all<<<3072, 256>>>(qw, kvw, pw, w1, w2);

    // 1) LN1 + shift + window partition
    ln_window_kernel<<<MTOK, 256>>>(x, g1, b1);

    // 2) q projection (N=256)
    mma_gemm<0,256><<<dim3(2, 1024), 256, GSMEM>>>(qb, nullptr, nullptr);

    // 3) kv projection (N=512)
    mma_gemm<1,256><<<dim3(4, 1024), 256, GSMEM>>>(kvb, nullptr, nullptr);

    // 4) windowed attention
    attn_kernel<<<dim3(2048, 8), 64>>>(maskm, btab);

    // 5) output projection + residuals + scatter -> x1   (ncu -s 5 target)
    mma_gemm<2,256><<<dim3(2, 1024), 256, GSMEM>>>(pb, x, nullptr);

    // 6) LN2
    ln2_kernel<<<MTOK, 256>>>(g2, b2);

    // 7) MLP up + GELU (N=1024)
    mma_gemm<3,256><<<dim3(8, 1024), 256, GSMEM>>>(bi1, nullptr, nullptr);

    // 8) MLP down + residual -> out (K=1024)
    mma_gemm<4,1024><<<dim3(2, 1024), 256, GSMEM>>>(bi2, nullptr, out);
}

// round 11
// speedup vs baseline: 2.1371x; 1.0183x over previous
#include <cuda_runtime.h>
#include <cuda_bf16.h>
#include <math.h>
#include <stdint.h>

// ---------------------------------------------------------------------------
// Problem constants
// ---------------------------------------------------------------------------
#define HHs     256
#define WWs     256
#define CCs     256
#define WS_     8
#define SHIFT_  4
#define MTOK    131072
#define QSCALE  0.17677669529663689f  // 1/sqrt(32)

// ---------------------------------------------------------------------------
// Arena (u32 words). Split tensors = two bf16 planes: hi[E], lo[E].
// ---------------------------------------------------------------------------
#define OFF_QIN_S  ((size_t)0)           // 33.5M  split (window order)
#define OFF_KVIN_S ((size_t)33554432)    // 33.5M  split
#define OFF_Q      ((size_t)67108864)    // 33.5M  fp32
#define OFF_KV     ((size_t)100663296)   // 67.1M  fp32
#define OFF_ATTN_S ((size_t)167772160)   // 33.5M  split
#define OFF_X1     ((size_t)201326592)   // 33.5M  fp32 (image order)
#define OFF_XN2_S  ((size_t)234881024)   // 33.5M  split
#define OFF_HID_S  ((size_t)268435456)   // 134.2M split
#define OFF_W      ((size_t)402653184)   // 786432 split weights
#define ARENA_F    ((size_t)403439616)

__device__ float g_arena[ARENA_F];

// weight sub-offsets (words) within OFF_W
#define WOFF_Q   0
#define WOFF_KV  65536
#define WOFF_P   196608
#define WOFF_W1  262144
#define WOFF_W2  524288

// ---------------------------------------------------------------------------
// Helpers (baseline PTX only: sm_80-era features, legal under .target sm_100)
// ---------------------------------------------------------------------------
__device__ __forceinline__ uint32_t s2u(const void* p) {
    uint32_t a;
    asm("{ .reg .u64 t; cvta.to.shared.u64 t, %1; cvt.u32.u64 %0, t; }" : "=r"(a) : "l"(p));
    return a;
}
__device__ __forceinline__ void cpa16(uint32_t saddr, const void* gptr) {
    asm volatile("cp.async.cg.shared.global [%0], [%1], 16;"
                 :: "r"(saddr), "l"(__cvta_generic_to_global(gptr)) : "memory");
}
__device__ __forceinline__ void cpa_commit() {
    asm volatile("cp.async.commit_group;" ::: "memory");
}
__device__ __forceinline__ void ldmx4(uint32_t* r, uint32_t addr) {
    asm volatile("ldmatrix.sync.aligned.m8n8.x4.shared.b16 {%0,%1,%2,%3}, [%4];"
                 : "=r"(r[0]), "=r"(r[1]), "=r"(r[2]), "=r"(r[3]) : "r"(addr));
}
__device__ __forceinline__ void mma16816(float& c0, float& c1, float& c2, float& c3,
                                         uint32_t a0, uint32_t a1, uint32_t a2, uint32_t a3,
                                         uint32_t b0, uint32_t b1) {
    asm volatile(
        "mma.sync.aligned.m16n8k16.row.col.f32.bf16.bf16.f32 "
        "{%0,%1,%2,%3}, {%4,%5,%6,%7}, {%8,%9}, {%0,%1,%2,%3};"
        : "+f"(c0), "+f"(c1), "+f"(c2), "+f"(c3)
        : "r"(a0), "r"(a1), "r"(a2), "r"(a3), "r"(b0), "r"(b1));
}
__device__ __forceinline__ float bf2f(uint32_t u16v) {
    return __uint_as_float(u16v << 16);
}
__device__ __forceinline__ void split2(float v, __nv_bfloat16& hi, __nv_bfloat16& lo) {
    hi = __float2bfloat16(v);
    lo = __float2bfloat16(v - __bfloat162float(hi));
}

// ---------------------------------------------------------------------------
// Weight split: all 5 weights in ONE launch.
// ---------------------------------------------------------------------------
__global__ void wsplit_all(const float* __restrict__ qw, const float* __restrict__ kvw,
                           const float* __restrict__ pw, const float* __restrict__ w1,
                           const float* __restrict__ w2) {
    int i = blockIdx.x * 256 + threadIdx.x;   // 0..786431
    const float* src; int n, woff, j = i;
    if (j < 65536)        { src = qw;  n = 65536;  woff = WOFF_Q; }
    else if ((j -= 65536) < 131072) { src = kvw; n = 131072; woff = WOFF_KV; }
    else if ((j -= 131072) < 65536) { src = pw;  n = 65536;  woff = WOFF_P; }
    else if ((j -= 65536) < 262144) { src = w1;  n = 262144; woff = WOFF_W1; }
    else { j -= 262144;               src = w2;  n = 262144; woff = WOFF_W2; }
    __nv_bfloat16* hi = (__nv_bfloat16*)((uint32_t*)g_arena + OFF_W + woff);
    __nv_bfloat16* lo = hi + n;
    __nv_bfloat16 h, l;
    split2(src[j], h, l);
    hi[j] = h; lo[j] = l;
}

// ---------------------------------------------------------------------------
// LN1 + shift-roll + window partition -> qin / kvin split planes
// ---------------------------------------------------------------------------
__global__ __launch_bounds__(256)
void ln_window_kernel(const float* __restrict__ x,
                      const float* __restrict__ g1,
                      const float* __restrict__ b1)
{
    int token = blockIdx.x, tid = threadIdx.x;
    int w_idx = token >> 6, n = token & 63;
    int b = w_idx >> 10, win = w_idx & 1023;
    int wh = win >> 5, wwc = win & 31;
    int r = n >> 3, cw = n & 7;
    int sh = (wh * WS_ + r + SHIFT_) & (HHs - 1);
    int sw = (wwc * WS_ + cw + SHIFT_) & (WWs - 1);

    __shared__ float red[16];
    float gg = g1[tid], bcoef = b1[tid];
    int warp = tid >> 5, lane = tid & 31;
    uint32_t* au = (uint32_t*)g_arena;

    for (int dsel = 0; dsel < 2; dsel++) {
        size_t base = ((((size_t)b * 2 + dsel) * HHs + sh) * WWs + sw) * CCs;
        float v = x[base + tid];
        float s = v, sq = v * v;
        #pragma unroll
        for (int o = 16; o; o >>= 1) {
            s  += __shfl_xor_sync(0xffffffffu, s,  o);
            sq += __shfl_xor_sync(0xffffffffu, sq, o);
        }
        if (lane == 0) { red[warp] = s; red[8 + warp] = sq; }
        __syncthreads();
        if (tid < 32) {
            float a = (tid < 8) ? red[tid] : 0.f;
            float c = (tid < 8) ? red[8 + tid] : 0.f;
            #pragma unroll
            for (int o = 4; o; o >>= 1) {
                a += __shfl_xor_sync(0xffffffffu, a, o);
                c += __shfl_xor_sync(0xffffffffu, c, o);
            }
            if (tid == 0) { red[0] = a; red[1] = c; }
        }
        __syncthreads();
        float mean = red[0] * (1.f / CCs);
        float var  = red[1] * (1.f / CCs) - mean * mean;
        float rstd = rsqrtf(var + 1e-5f);
        float outv = (v - mean) * rstd * gg + bcoef;
        __nv_bfloat16 h, l;
        split2(outv, h, l);
        size_t e = (size_t)token * CCs + tid;
        __nv_bfloat16* hp = (__nv_bfloat16*)(au + (dsel == 0 ? OFF_QIN_S : OFF_KVIN_S));
        hp[e] = h;
        hp[(size_t)MTOK * CCs + e] = l;
        __syncthreads();
    }
}

// ---------------------------------------------------------------------------
// LN2: x1 fp32 -> xn2 split planes
// ---------------------------------------------------------------------------
__global__ __launch_bounds__(256)
void ln2_kernel(const float* __restrict__ g2, const float* __restrict__ b2)
{
    int token = blockIdx.x, tid = threadIdx.x;
    __shared__ float red[16];
    size_t base = (size_t)token * CCs;
    float v = g_arena[OFF_X1 + base + tid];
    float s = v, sq = v * v;
    #pragma unroll
    for (int o = 16; o; o >>= 1) {
        s  += __shfl_xor_sync(0xffffffffu, s,  o);
        sq += __shfl_xor_sync(0xffffffffu, sq, o);
    }
    int warp = tid >> 5, lane = tid & 31;
    if (lane == 0) { red[warp] = s; red[8 + warp] = sq; }
    __syncthreads();
    if (tid < 32) {
        float a = (tid < 8) ? red[tid] : 0.f;
        float c = (tid < 8) ? red[8 + tid] : 0.f;
        #pragma unroll
        for (int o = 4; o; o >>= 1) {
            a += __shfl_xor_sync(0xffffffffu, a, o);
            c += __shfl_xor_sync(0xffffffffu, c, o);
        }
        if (tid == 0) { red[0] = a; red[1] = c; }
    }
    __syncthreads();
    float mean = red[0] * (1.f / CCs);
    float var  = red[1] * (1.f / CCs) - mean * mean;
    float rstd = rsqrtf(var + 1e-5f);
    float outv = (v - mean) * rstd * g2[tid] + b2[tid];
    __nv_bfloat16 h, l;
    split2(outv, h, l);
    __nv_bfloat16* hp = (__nv_bfloat16*)((uint32_t*)g_arena + OFF_XN2_S);
    hp[base + tid] = h;
    hp[(size_t)MTOK * CCs + base + tid] = l;
}

// ---------------------------------------------------------------------------
// Split-bf16 warp-MMA GEMM (mma.sync m16n8k16, 3 passes: hh, hl, lh).
// CTA 128x128, BK=16, 8 warps (warp tile 64x32).
// 4-stage cp.async pipeline, ONE __syncthreads per chunk (cutlass-style):
//   prologue loads stages 0-2; iteration c: wait_group 2 (stage c ready),
//   sync, issue stage c+3 (or empty commit to keep group accounting exact),
//   compute stage c. Overwrite-safety: stage (c+3)&3 == (c-1)&3 was last read
//   in compute(c-1), finished by every warp before this iteration's sync.
// ---------------------------------------------------------------------------
#define PLANE_B 6144        // 128 rows * 48 B
#define STG_B   24576       // Ahi | Alo | Bhi | Blo
#define NSTAGE  4
#define GSMEM   (NSTAGE * STG_B) // 98304 (needs opt-in via cudaFuncSetAttribute)

template<int MODE, int KDIM>
__global__ __launch_bounds__(256, 2)
void mma_gemm(const float* __restrict__ bias,
              const float* __restrict__ xsrc,
              float* __restrict__ dout)
{
    constexpr int NC = KDIM / 16;
    constexpr size_t E_A = (size_t)MTOK * KDIM;
    constexpr size_t E_B = (MODE == 0) ? 65536 : (MODE == 1) ? 131072 :
                           (MODE == 2) ? 65536 : 262144;
    constexpr size_t AOFF = (MODE == 0) ? OFF_QIN_S : (MODE == 1) ? OFF_KVIN_S :
                            (MODE == 2) ? OFF_ATTN_S : (MODE == 3) ? OFF_XN2_S : OFF_HID_S;
    constexpr size_t WO = OFF_W + ((MODE == 0) ? WOFF_Q : (MODE == 1) ? WOFF_KV :
                                   (MODE == 2) ? WOFF_P : (MODE == 3) ? WOFF_W1 : WOFF_W2);

    extern __shared__ char smem[];
    uint32_t sbase = s2u(smem);

    int tid = threadIdx.x;
    int wid = tid >> 5, lane = tid & 31;
    int g = lane >> 2, tg = lane & 3;
    int warpM = wid & 1, warpN = wid >> 1;
    int m0 = blockIdx.y * 128;
    int n0 = blockIdx.x * 128;

    uint32_t* au = (uint32_t*)g_arena;
    const __nv_bfloat16* Ahi = (const __nv_bfloat16*)(au + AOFF);
    const __nv_bfloat16* Alo = Ahi + E_A;
    const __nv_bfloat16* Bhi = (const __nv_bfloat16*)(au + WO);
    const __nv_bfloat16* Blo = Bhi + E_B;

    float acc[4][4][4];
    #pragma unroll
    for (int i = 0; i < 4; i++)
        #pragma unroll
        for (int j = 0; j < 4; j++)
            #pragma unroll
            for (int k = 0; k < 4; k++) acc[i][j][k] = 0.f;

    // ldmatrix per-lane source rows/offsets (within-tile; constant per thread)
    int l7 = lane & 7;
    int a_row = warpM * 64 + l7 + ((lane >> 3) & 1) * 8;   // + mt*16
    int a_kof = (lane >> 4) * 8;
    int b_row = warpN * 32 + l7 + ((lane >> 4) & 1) * 8;   // + pair*16
    int b_kof = ((lane >> 3) & 1) * 8;

    auto load_chunk = [&](int s, int kc0) {
        uint32_t sb = sbase + s * STG_B;
        int row = tid >> 1, k8 = (tid & 1) * 8;
        uint32_t so = sb + row * 48 + k8 * 2;
        size_t ga = (size_t)(m0 + row) * KDIM + kc0 + k8;
        size_t gb = (size_t)(n0 + row) * KDIM + kc0 + k8;
        cpa16(so,               Ahi + ga);
        cpa16(so + PLANE_B,     Alo + ga);
        cpa16(so + 2 * PLANE_B, Bhi + gb);
        cpa16(so + 3 * PLANE_B, Blo + gb);
        cpa_commit();
    };

    auto compute = [&](int s) {
        uint32_t stg = sbase + s * STG_B;
        #pragma unroll
        for (int p = 0; p < 3; p++) {
            uint32_t aB = stg + (p == 2 ? PLANE_B : 0);
            uint32_t bB = stg + 2 * PLANE_B + (p == 1 ? PLANE_B : 0);
            uint32_t a[4][4], b[4][2];
            #pragma unroll
            for (int mt = 0; mt < 4; mt++)
                ldmx4(a[mt], aB + ((a_row + mt * 16) * 24 + a_kof) * 2);
            // pair 0 -> b[0], b[1];  pair 1 -> b[2], b[3]
            {
                uint32_t t4[4];
                ldmx4(t4, bB + (b_row * 24 + b_kof) * 2);
                b[0][0] = t4[0]; b[0][1] = t4[1]; b[1][0] = t4[2]; b[1][1] = t4[3];
                ldmx4(t4, bB + ((b_row + 16) * 24 + b_kof) * 2);
                b[2][0] = t4[0]; b[2][1] = t4[1]; b[3][0] = t4[2]; b[3][1] = t4[3];
            }
            #pragma unroll
            for (int mt = 0; mt < 4; mt++)
                #pragma unroll
                for (int nt = 0; nt < 4; nt++)
                    mma16816(acc[mt][nt][0], acc[mt][nt][1], acc[mt][nt][2], acc[mt][nt][3],
                             a[mt][0], a[mt][1], a[mt][2], a[mt][3],
                             b[nt][0], b[nt][1]);
        }
    };

    // ---- 4-stage pipeline, one sync per chunk ----
    load_chunk(0, 0);
    load_chunk(1, 16);
    load_chunk(2, 32);
    for (int c = 0; c < NC; c++) {
        asm volatile("cp.async.wait_group 2;" ::: "memory");
        __syncthreads();
        if (c + 3 < NC) load_chunk((c + 3) & 3, (c + 3) * 16);
        else            cpa_commit();   // empty group keeps wait_group accounting exact
        compute(c & 3);
    }

    // ------------------------------- epilogue -------------------------------
    int tg2 = tg * 2;
    int coln[4];
    float2 bb[4];
    #pragma unroll
    for (int nt = 0; nt < 4; nt++) {
        coln[nt] = n0 + warpN * 32 + nt * 8 + tg2;
        bb[nt] = *(const float2*)(bias + coln[nt]);
    }

    #pragma unroll
    for (int mt = 0; mt < 4; mt++) {
        #pragma unroll
        for (int rr = 0; rr < 2; rr++) {
            int row = m0 + warpM * 64 + mt * 16 + g + rr * 8;

            size_t img = 0, ximg = 0;
            if (MODE == 2) {
                int w_idx = row >> 6, nn = row & 63;
                int b = w_idx >> 10, win = w_idx & 1023;
                int wh = win >> 5, wwc = win & 31;
                int r = nn >> 3, cw = nn & 7;
                int hi_ = (wh * WS_ + r + SHIFT_) & (HHs - 1);
                int wi_ = (wwc * WS_ + cw + SHIFT_) & (WWs - 1);
                img  = (((size_t)b * HHs + hi_) * WWs + wi_) * CCs;
                ximg = ((((size_t)b * 2) * HHs + hi_) * WWs + wi_) * CCs;
            }

            #pragma unroll
            for (int nt = 0; nt < 4; nt++) {
                int col = coln[nt];
                float v0 = acc[mt][nt][rr * 2 + 0] + bb[nt].x;
                float v1 = acc[mt][nt][rr * 2 + 1] + bb[nt].y;

                if (MODE == 0) {
                    *(float2*)(g_arena + OFF_Q + (size_t)row * 256 + col) =
                        make_float2(v0 * QSCALE, v1 * QSCALE);
                } else if (MODE == 1) {
                    *(float2*)(g_arena + OFF_KV + (size_t)row * 512 + col) =
                        make_float2(v0, v1);
                } else if (MODE == 2) {
                    size_t widx = (size_t)row * 128 + (col >> 1);
                    uint32_t hq = au[OFF_QIN_S + widx];
                    uint32_t lq = au[OFF_QIN_S + 16777216 + widx];
                    float2 sc = *(const float2*)(xsrc + ximg + col);
                    v0 += bf2f(hq & 0xFFFFu) + bf2f(lq & 0xFFFFu) + sc.x;
                    v1 += bf2f(hq >> 16)     + bf2f(lq >> 16)     + sc.y;
                    *(float2*)(g_arena + OFF_X1 + img + col) = make_float2(v0, v1);
                } else if (MODE == 3) {
                    float g0 = v0 * normcdff(v0);
                    float g1 = v1 * normcdff(v1);
                    __nv_bfloat16 h0, l0, h1, l1;
                    split2(g0, h0, l0); split2(g1, h1, l1);
                    size_t widx = (size_t)row * 512 + (col >> 1);
                    au[OFF_HID_S + widx] =
                        (uint32_t)__bfloat16_as_ushort(h0) |
                        ((uint32_t)__bfloat16_as_ushort(h1) << 16);
                    au[OFF_HID_S + 67108864 + widx] =
                        (uint32_t)__bfloat16_as_ushort(l0) |
                        ((uint32_t)__bfloat16_as_ushort(l1) << 16);
                } else { // MODE 4
                    float2 x1v = *(const float2*)(g_arena + OFF_X1 + (size_t)row * 256 + col);
                    *(float2*)(dout + (size_t)row * 256 + col) =
                        make_float2(v0 + x1v.x, v1 + x1v.y);
                }
            }
        }
    }
}

// ---------------------------------------------------------------------------
// Windowed attention. One block per (window, head). Reads q/kv fp32,
// writes attn split planes.
// ---------------------------------------------------------------------------
__global__ __launch_bounds__(64)
void attn_kernel(const float* __restrict__ mask, const float* __restrict__ btab)
{
    int w_idx = blockIdx.x, hh = blockIdx.y, t = threadIdx.x;
    __shared__ float ksh[64 * 36];
    __shared__ float vsh[64 * 36];
    __shared__ float sbias[225];

    for (int i = t; i < 225; i += 64) sbias[i] = btab[i * 8 + hh];

    const float* kvp = g_arena + OFF_KV + ((size_t)w_idx * 64 + t) * 512 + hh * 32;
    #pragma unroll
    for (int q4 = 0; q4 < 8; q4++) {
        *(float4*)&ksh[t * 36 + q4 * 4] = *(const float4*)(kvp + q4 * 4);
        *(float4*)&vsh[t * 36 + q4 * 4] = *(const float4*)(kvp + 256 + q4 * 4);
    }

    float q[32];
    const float* qp = g_arena + OFF_Q + ((size_t)w_idx * 64 + t) * 256 + hh * 32;
    #pragma unroll
    for (int q4 = 0; q4 < 8; q4++) {
        float4 qq = *(const float4*)(qp + q4 * 4);
        q[q4*4+0] = qq.x; q[q4*4+1] = qq.y; q[q4*4+2] = qq.z; q[q4*4+3] = qq.w;
    }
    __syncthreads();

    int r1 = t >> 3, c1 = t & 7;
    int win = w_idx & 1023;
    const float* mrow = mask + ((size_t)win * 64 + t) * 64;

    float s[64];
    #pragma unroll
    for (int m = 0; m < 64; m++) {
        float acc = 0.f;
        #pragma unroll
        for (int d4 = 0; d4 < 8; d4++) {
            float4 kk = *(const float4*)&ksh[m * 36 + d4 * 4];
            acc += q[d4*4+0]*kk.x + q[d4*4+1]*kk.y + q[d4*4+2]*kk.z + q[d4*4+3]*kk.w;
        }
        int r2 = m >> 3, c2 = m & 7;
        s[m] = acc + sbias[(r1 - r2 + 7) * 15 + (c1 - c2 + 7)] + mrow[m];
    }

    float mx = -1e30f;
    #pragma unroll
    for (int m = 0; m < 64; m++) mx = fmaxf(mx, s[m]);
    float sum = 0.f;
    #pragma unroll
    for (int m = 0; m < 64; m++) { s[m] = __expf(s[m] - mx); sum += s[m]; }
    float inv = 1.f / sum;

    float o[32];
    #pragma unroll
    for (int j = 0; j < 32; j++) o[j] = 0.f;
    #pragma unroll
    for (int m = 0; m < 64; m++) {
        float p = s[m];
        #pragma unroll
        for (int d4 = 0; d4 < 8; d4++) {
            float4 vv = *(const float4*)&vsh[m * 36 + d4 * 4];
            o[d4*4+0] += p * vv.x; o[d4*4+1] += p * vv.y;
            o[d4*4+2] += p * vv.z; o[d4*4+3] += p * vv.w;
        }
    }

    // split-pack output (hi/lo planes)
    uint32_t* au = (uint32_t*)g_arena;
    size_t base = ((size_t)w_idx * 64 + t) * 256 + hh * 32;
    #pragma unroll
    for (int j = 0; j < 16; j++) {
        float a = o[2*j] * inv, b = o[2*j+1] * inv;
        __nv_bfloat16 ha, la, hb, lb;
        split2(a, ha, la); split2(b, hb, lb);
        size_t widx = (base >> 1) + j;
        au[OFF_ATTN_S + widx] =
            (uint32_t)__bfloat16_as_ushort(ha) | ((uint32_t)__bfloat16_as_ushort(hb) << 16);
        au[OFF_ATTN_S + 16777216 + widx] =
            (uint32_t)__bfloat16_as_ushort(la) | ((uint32_t)__bfloat16_as_ushort(lb) << 16);
    }
}

// ---------------------------------------------------------------------------
// Launch. 96KB dynamic smem needs the attribute opt-in (proven safe in R2).
// ---------------------------------------------------------------------------
extern "C" void kernel_launch(void* const* d_in, const int* in_sizes, int n_in,
                              void* d_out, int out_size)
{
    const float* x     = (const float*)d_in[0];
    const float* maskm = (const float*)d_in[1];
    const float* g1    = (const float*)d_in[2];
    const float* b1    = (const float*)d_in[3];
    const float* qw    = (const float*)d_in[4];
    const float* qb    = (const float*)d_in[5];
    const float* kvw   = (const float*)d_in[6];
    const float* kvb   = (const float*)d_in[7];
    const float* pw    = (const float*)d_in[8];
    const float* pb    = (const float*)d_in[9];
    const float* btab  = (const float*)d_in[10];
    const float* g2    = (const float*)d_in[11];
    const float* b2    = (const float*)d_in[12];
    const float* w1    = (const float*)d_in[13];
    const float* bi1   = (const float*)d_in[14];
    const float* w2    = (const float*)d_in[15];
    const float* bi2   = (const float*)d_in[16];
    float* out = (float*)d_out;

    cudaFuncSetAttribute(mma_gemm<0,256>,  cudaFuncAttributeMaxDynamicSharedMemorySize, GSMEM);
    cudaFuncSetAttribute(mma_gemm<1,256>,  cudaFuncAttributeMaxDynamicSharedMemorySize, GSMEM);
    cudaFuncSetAttribute(mma_gemm<2,256>,  cudaFuncAttributeMaxDynamicSharedMemorySize, GSMEM);
    cudaFuncSetAttribute(mma_gemm<3,256>,  cudaFuncAttributeMaxDynamicSharedMemorySize, GSMEM);
    cudaFuncSetAttribute(mma_gemm<4,1024>, cudaFuncAttributeMaxDynamicSharedMemorySize, GSMEM);

    // 0) split all weights (single launch)
    wsplit_all<<<3072, 256>>>(qw, kvw, pw, w1, w2);

    // 1) LN1 + shift + window partition
    ln_window_kernel<<<MTOK, 256>>>(x, g1, b1);

    // 2) q projection (N=256)
    mma_gemm<0,256><<<dim3(2, 1024), 256, GSMEM>>>(qb, nullptr, nullptr);

    // 3) kv projection (N=512)
    mma_gemm<1,256><<<dim3(4, 1024), 256, GSMEM>>>(kvb, nullptr, nullptr);

    // 4) windowed attention
    attn_kernel<<<dim3(2048, 8), 64>>>(maskm, btab);

    // 5) output projection + residuals + scatter -> x1
    mma_gemm<2,256><<<dim3(2, 1024), 256, GSMEM>>>(pb, x, nullptr);

    // 6) LN2
    ln2_kernel<<<MTOK, 256>>>(g2, b2);

    // 7) MLP up + GELU (N=1024)
    mma_gemm<3,256><<<dim3(8, 1024), 256, GSMEM>>>(bi1, nullptr, nullptr);

    // 8) MLP down + residual -> out (K=1024)
    mma_gemm<4,1024><<<dim3(2, 1024), 256, GSMEM>>>(bi2, nullptr, out);
}

// round 12
// speedup vs baseline: 2.5012x; 1.1704x over previous
#include <cuda_runtime.h>
#include <cuda_bf16.h>
#include <cuda_fp16.h>
#include <math.h>
#include <stdint.h>

// ---------------------------------------------------------------------------
// Problem constants
// ---------------------------------------------------------------------------
#define HHs     256
#define WWs     256
#define CCs     256
#define WS_     8
#define SHIFT_  4
#define MTOK    131072
#define QSCALE  0.17677669529663689f  // 1/sqrt(32)

// ---------------------------------------------------------------------------
// Arena (u32 words). Split activations = two fp16 planes hi[E], lo[E]
// (E halves each = E words total). Weights = single fp16 plane (E/2 words).
// ---------------------------------------------------------------------------
#define OFF_QIN_S  ((size_t)0)           // 33.5M  split (window order)
#define OFF_KVIN_S ((size_t)33554432)    // 33.5M  split
#define OFF_Q      ((size_t)67108864)    // 33.5M  fp32
#define OFF_KV     ((size_t)100663296)   // 67.1M  fp32
#define OFF_ATTN_S ((size_t)167772160)   // 33.5M  split
#define OFF_X1     ((size_t)201326592)   // 33.5M  fp32 (image order)
#define OFF_XN2_S  ((size_t)234881024)   // 33.5M  split
#define OFF_HID_S  ((size_t)268435456)   // 134.2M split
#define OFF_W      ((size_t)402653184)   // fp16 weights (hi only)
#define ARENA_F    ((size_t)403439616)

__device__ float g_arena[ARENA_F];

// weight sub-offsets (u32 words) within OFF_W — single fp16 plane each
#define WOFF_Q   0
#define WOFF_KV  65536
#define WOFF_P   196608
#define WOFF_W1  262144
#define WOFF_W2  524288

// ---------------------------------------------------------------------------
// Helpers (baseline PTX only)
// ---------------------------------------------------------------------------
__device__ __forceinline__ uint32_t s2u(const void* p) {
    uint32_t a;
    asm("{ .reg .u64 t; cvta.to.shared.u64 t, %1; cvt.u32.u64 %0, t; }" : "=r"(a) : "l"(p));
    return a;
}
__device__ __forceinline__ void cpa16(uint32_t saddr, const void* gptr) {
    asm volatile("cp.async.cg.shared.global [%0], [%1], 16;"
                 :: "r"(saddr), "l"(__cvta_generic_to_global(gptr)) : "memory");
}
__device__ __forceinline__ void cpa_commit() {
    asm volatile("cp.async.commit_group;" ::: "memory");
}
__device__ __forceinline__ void ldmx4(uint32_t* r, uint32_t addr) {
    asm volatile("ldmatrix.sync.aligned.m8n8.x4.shared.b16 {%0,%1,%2,%3}, [%4];"
                 : "=r"(r[0]), "=r"(r[1]), "=r"(r[2]), "=r"(r[3]) : "r"(addr));
}
__device__ __forceinline__ void mma16816h(float& c0, float& c1, float& c2, float& c3,
                                          uint32_t a0, uint32_t a1, uint32_t a2, uint32_t a3,
                                          uint32_t b0, uint32_t b1) {
    asm volatile(
        "mma.sync.aligned.m16n8k16.row.col.f32.f16.f16.f32 "
        "{%0,%1,%2,%3}, {%4,%5,%6,%7}, {%8,%9}, {%0,%1,%2,%3};"
        : "+f"(c0), "+f"(c1), "+f"(c2), "+f"(c3)
        : "r"(a0), "r"(a1), "r"(a2), "r"(a3), "r"(b0), "r"(b1));
}
__device__ __forceinline__ float h2f16(uint32_t u16v) {
    return __half2float(__ushort_as_half((unsigned short)u16v));
}
// fp32 -> fp16 hi + fp16 lo (hi = RN(v), lo = RN(v - hi)); ~22-bit accurate
__device__ __forceinline__ void split2h(float v, __half& hi, __half& lo) {
    hi = __float2half(v);
    lo = __float2half(v - __half2float(hi));
}

// ---------------------------------------------------------------------------
// Weight convert: all 5 weights -> single fp16 plane, ONE launch.
// ---------------------------------------------------------------------------
__global__ void wsplit_all(const float* __restrict__ qw, const float* __restrict__ kvw,
                           const float* __restrict__ pw, const float* __restrict__ w1,
                           const float* __restrict__ w2) {
    int i = blockIdx.x * 256 + threadIdx.x;   // 0..786431
    const float* src; int woff, j = i;
    if (j < 65536)        { src = qw;  woff = WOFF_Q; }
    else if ((j -= 65536) < 131072) { src = kvw; woff = WOFF_KV; }
    else if ((j -= 131072) < 65536) { src = pw;  woff = WOFF_P; }
    else if ((j -= 65536) < 262144) { src = w1;  woff = WOFF_W1; }
    else { j -= 262144;               src = w2;  woff = WOFF_W2; }
    __half* hp = (__half*)((uint32_t*)g_arena + OFF_W + woff);
    hp[j] = __float2half(src[j]);
}

// ---------------------------------------------------------------------------
// LN1 + shift-roll + window partition -> qin / kvin split fp16 planes
// ---------------------------------------------------------------------------
__global__ __launch_bounds__(256)
void ln_window_kernel(const float* __restrict__ x,
                      const float* __restrict__ g1,
                      const float* __restrict__ b1)
{
    int token = blockIdx.x, tid = threadIdx.x;
    int w_idx = token >> 6, n = token & 63;
    int b = w_idx >> 10, win = w_idx & 1023;
    int wh = win >> 5, wwc = win & 31;
    int r = n >> 3, cw = n & 7;
    int sh = (wh * WS_ + r + SHIFT_) & (HHs - 1);
    int sw = (wwc * WS_ + cw + SHIFT_) & (WWs - 1);

    __shared__ float red[16];
    float gg = g1[tid], bcoef = b1[tid];
    int warp = tid >> 5, lane = tid & 31;
    uint32_t* au = (uint32_t*)g_arena;

    for (int dsel = 0; dsel < 2; dsel++) {
        size_t base = ((((size_t)b * 2 + dsel) * HHs + sh) * WWs + sw) * CCs;
        float v = x[base + tid];
        float s = v, sq = v * v;
        #pragma unroll
        for (int o = 16; o; o >>= 1) {
            s  += __shfl_xor_sync(0xffffffffu, s,  o);
            sq += __shfl_xor_sync(0xffffffffu, sq, o);
        }
        if (lane == 0) { red[warp] = s; red[8 + warp] = sq; }
        __syncthreads();
        if (tid < 32) {
            float a = (tid < 8) ? red[tid] : 0.f;
            float c = (tid < 8) ? red[8 + tid] : 0.f;
            #pragma unroll
            for (int o = 4; o; o >>= 1) {
                a += __shfl_xor_sync(0xffffffffu, a, o);
                c += __shfl_xor_sync(0xffffffffu, c, o);
            }
            if (tid == 0) { red[0] = a; red[1] = c; }
        }
        __syncthreads();
        float mean = red[0] * (1.f / CCs);
        float var  = red[1] * (1.f / CCs) - mean * mean;
        float rstd = rsqrtf(var + 1e-5f);
        float outv = (v - mean) * rstd * gg + bcoef;
        __half h, l;
        split2h(outv, h, l);
        size_t e = (size_t)token * CCs + tid;
        __half* hp = (__half*)(au + (dsel == 0 ? OFF_QIN_S : OFF_KVIN_S));
        hp[e] = h;
        hp[(size_t)MTOK * CCs + e] = l;
        __syncthreads();
    }
}

// ---------------------------------------------------------------------------
// LN2: x1 fp32 -> xn2 split fp16 planes
// ---------------------------------------------------------------------------
__global__ __launch_bounds__(256)
void ln2_kernel(const float* __restrict__ g2, const float* __restrict__ b2)
{
    int token = blockIdx.x, tid = threadIdx.x;
    __shared__ float red[16];
    size_t base = (size_t)token * CCs;
    float v = g_arena[OFF_X1 + base + tid];
    float s = v, sq = v * v;
    #pragma unroll
    for (int o = 16; o; o >>= 1) {
        s  += __shfl_xor_sync(0xffffffffu, s,  o);
        sq += __shfl_xor_sync(0xffffffffu, sq, o);
    }
    int warp = tid >> 5, lane = tid & 31;
    if (lane == 0) { red[warp] = s; red[8 + warp] = sq; }
    __syncthreads();
    if (tid < 32) {
        float a = (tid < 8) ? red[tid] : 0.f;
        float c = (tid < 8) ? red[8 + tid] : 0.f;
        #pragma unroll
        for (int o = 4; o; o >>= 1) {
            a += __shfl_xor_sync(0xffffffffu, a, o);
            c += __shfl_xor_sync(0xffffffffu, c, o);
        }
        if (tid == 0) { red[0] = a; red[1] = c; }
    }
    __syncthreads();
    float mean = red[0] * (1.f / CCs);
    float var  = red[1] * (1.f / CCs) - mean * mean;
    float rstd = rsqrtf(var + 1e-5f);
    float outv = (v - mean) * rstd * g2[tid] + b2[tid];
    __half h, l;
    split2h(outv, h, l);
    __half* hp = (__half*)((uint32_t*)g_arena + OFF_XN2_S);
    hp[base + tid] = h;
    hp[(size_t)MTOK * CCs + base + tid] = l;
}

// ---------------------------------------------------------------------------
// 2-pass fp16 warp-MMA GEMM: out = A_hi*B + A_lo*B  (B single fp16 plane).
// CTA 128x128, BK=16, 8 warps (warp tile 64x32).
// 4-stage cp.async pipeline, one __syncthreads per chunk.
// Per chunk: 10 LDSM (8 A + 2 B, B shared by both passes), 32 HMMA.
// ---------------------------------------------------------------------------
#define PLANE_B 6144        // 128 rows * 48 B (stride 24 halves)
#define STG_B   18432       // Ahi | Alo | B
#define NSTAGE  4
#define GSMEM   (NSTAGE * STG_B) // 73728 (opt-in attribute)

template<int MODE, int KDIM>
__global__ __launch_bounds__(256, 2)
void mma_gemm(const float* __restrict__ bias,
              const float* __restrict__ xsrc,
              float* __restrict__ dout)
{
    constexpr int NC = KDIM / 16;
    constexpr size_t E_A = (size_t)MTOK * KDIM;
    constexpr size_t AOFF = (MODE == 0) ? OFF_QIN_S : (MODE == 1) ? OFF_KVIN_S :
                            (MODE == 2) ? OFF_ATTN_S : (MODE == 3) ? OFF_XN2_S : OFF_HID_S;
    constexpr size_t WO = OFF_W + ((MODE == 0) ? WOFF_Q : (MODE == 1) ? WOFF_KV :
                                   (MODE == 2) ? WOFF_P : (MODE == 3) ? WOFF_W1 : WOFF_W2);

    extern __shared__ char smem[];
    uint32_t sbase = s2u(smem);

    int tid = threadIdx.x;
    int wid = tid >> 5, lane = tid & 31;
    int g = lane >> 2, tg = lane & 3;
    int warpM = wid & 1, warpN = wid >> 1;
    int m0 = blockIdx.y * 128;
    int n0 = blockIdx.x * 128;

    uint32_t* au = (uint32_t*)g_arena;
    const __half* Ahi = (const __half*)(au + AOFF);
    const __half* Alo = Ahi + E_A;
    const __half* Bw  = (const __half*)(au + WO);

    float acc[4][4][4];
    #pragma unroll
    for (int i = 0; i < 4; i++)
        #pragma unroll
        for (int j = 0; j < 4; j++)
            #pragma unroll
            for (int k = 0; k < 4; k++) acc[i][j][k] = 0.f;

    // ldmatrix per-lane source rows/offsets
    int l7 = lane & 7;
    int a_row = warpM * 64 + l7 + ((lane >> 3) & 1) * 8;   // + mt*16
    int a_kof = (lane >> 4) * 8;
    int b_row = warpN * 32 + l7 + ((lane >> 4) & 1) * 8;   // + pair*16
    int b_kof = ((lane >> 3) & 1) * 8;

    auto load_chunk = [&](int s, int kc0) {
        uint32_t sb = sbase + s * STG_B;
        int row = tid >> 1, k8 = (tid & 1) * 8;
        uint32_t so = sb + row * 48 + k8 * 2;
        size_t ga = (size_t)(m0 + row) * KDIM + kc0 + k8;
        size_t gb = (size_t)(n0 + row) * KDIM + kc0 + k8;
        cpa16(so,               Ahi + ga);
        cpa16(so + PLANE_B,     Alo + ga);
        cpa16(so + 2 * PLANE_B, Bw + gb);
        cpa_commit();
    };

    auto compute = [&](int s) {
        uint32_t stg = sbase + s * STG_B;
        // B fragments: loaded ONCE, shared by both passes
        uint32_t b[4][2];
        {
            uint32_t bB = stg + 2 * PLANE_B;
            uint32_t t4[4];
            ldmx4(t4, bB + (b_row * 24 + b_kof) * 2);
            b[0][0] = t4[0]; b[0][1] = t4[1]; b[1][0] = t4[2]; b[1][1] = t4[3];
            ldmx4(t4, bB + ((b_row + 16) * 24 + b_kof) * 2);
            b[2][0] = t4[0]; b[2][1] = t4[1]; b[3][0] = t4[2]; b[3][1] = t4[3];
        }
        #pragma unroll
        for (int p = 0; p < 2; p++) {
            uint32_t aB = stg + p * PLANE_B;
            uint32_t a[4][4];
            #pragma unroll
            for (int mt = 0; mt < 4; mt++)
                ldmx4(a[mt], aB + ((a_row + mt * 16) * 24 + a_kof) * 2);
            #pragma unroll
            for (int mt = 0; mt < 4; mt++)
                #pragma unroll
                for (int nt = 0; nt < 4; nt++)
                    mma16816h(acc[mt][nt][0], acc[mt][nt][1], acc[mt][nt][2], acc[mt][nt][3],
                              a[mt][0], a[mt][1], a[mt][2], a[mt][3],
                              b[nt][0], b[nt][1]);
        }
    };

    // ---- 4-stage pipeline, one sync per chunk ----
    load_chunk(0, 0);
    load_chunk(1, 16);
    load_chunk(2, 32);
    for (int c = 0; c < NC; c++) {
        asm volatile("cp.async.wait_group 2;" ::: "memory");
        __syncthreads();
        if (c + 3 < NC) load_chunk((c + 3) & 3, (c + 3) * 16);
        else            cpa_commit();
        compute(c & 3);
    }

    // ------------------------------- epilogue -------------------------------
    int tg2 = tg * 2;
    int coln[4];
    float2 bb[4];
    #pragma unroll
    for (int nt = 0; nt < 4; nt++) {
        coln[nt] = n0 + warpN * 32 + nt * 8 + tg2;
        bb[nt] = *(const float2*)(bias + coln[nt]);
    }

    #pragma unroll
    for (int mt = 0; mt < 4; mt++) {
        #pragma unroll
        for (int rr = 0; rr < 2; rr++) {
            int row = m0 + warpM * 64 + mt * 16 + g + rr * 8;

            size_t img = 0, ximg = 0;
            if (MODE == 2) {
                int w_idx = row >> 6, nn = row & 63;
                int b = w_idx >> 10, win = w_idx & 1023;
                int wh = win >> 5, wwc = win & 31;
                int r = nn >> 3, cw = nn & 7;
                int hi_ = (wh * WS_ + r + SHIFT_) & (HHs - 1);
                int wi_ = (wwc * WS_ + cw + SHIFT_) & (WWs - 1);
                img  = (((size_t)b * HHs + hi_) * WWs + wi_) * CCs;
                ximg = ((((size_t)b * 2) * HHs + hi_) * WWs + wi_) * CCs;
            }

            #pragma unroll
            for (int nt = 0; nt < 4; nt++) {
                int col = coln[nt];
                float v0 = acc[mt][nt][rr * 2 + 0] + bb[nt].x;
                float v1 = acc[mt][nt][rr * 2 + 1] + bb[nt].y;

                if (MODE == 0) {
                    *(float2*)(g_arena + OFF_Q + (size_t)row * 256 + col) =
                        make_float2(v0 * QSCALE, v1 * QSCALE);
                } else if (MODE == 1) {
                    *(float2*)(g_arena + OFF_KV + (size_t)row * 512 + col) =
                        make_float2(v0, v1);
                } else if (MODE == 2) {
                    size_t widx = (size_t)row * 128 + (col >> 1);
                    uint32_t hq = au[OFF_QIN_S + widx];
                    uint32_t lq = au[OFF_QIN_S + 16777216 + widx];
                    float2 sc = *(const float2*)(xsrc + ximg + col);
                    v0 += h2f16(hq & 0xFFFFu) + h2f16(lq & 0xFFFFu) + sc.x;
                    v1 += h2f16(hq >> 16)     + h2f16(lq >> 16)     + sc.y;
                    *(float2*)(g_arena + OFF_X1 + img + col) = make_float2(v0, v1);
                } else if (MODE == 3) {
                    float g0 = v0 * normcdff(v0);
                    float g1 = v1 * normcdff(v1);
                    __half h0, l0, h1, l1;
                    split2h(g0, h0, l0); split2h(g1, h1, l1);
                    size_t widx = (size_t)row * 512 + (col >> 1);
                    au[OFF_HID_S + widx] =
                        (uint32_t)__half_as_ushort(h0) |
                        ((uint32_t)__half_as_ushort(h1) << 16);
                    au[OFF_HID_S + 67108864 + widx] =
                        (uint32_t)__half_as_ushort(l0) |
                        ((uint32_t)__half_as_ushort(l1) << 16);
                } else { // MODE 4
                    float2 x1v = *(const float2*)(g_arena + OFF_X1 + (size_t)row * 256 + col);
                    *(float2*)(dout + (size_t)row * 256 + col) =
                        make_float2(v0 + x1v.x, v1 + x1v.y);
                }
            }
        }
    }
}

// ---------------------------------------------------------------------------
// Windowed attention. Reads q/kv fp32, writes attn split fp16 planes.
// ---------------------------------------------------------------------------
__global__ __launch_bounds__(64)
void attn_kernel(const float* __restrict__ mask, const float* __restrict__ btab)
{
    int w_idx = blockIdx.x, hh = blockIdx.y, t = threadIdx.x;
    __shared__ float ksh[64 * 36];
    __shared__ float vsh[64 * 36];
    __shared__ float sbias[225];

    for (int i = t; i < 225; i += 64) sbias[i] = btab[i * 8 + hh];

    const float* kvp = g_arena + OFF_KV + ((size_t)w_idx * 64 + t) * 512 + hh * 32;
    #pragma unroll
    for (int q4 = 0; q4 < 8; q4++) {
        *(float4*)&ksh[t * 36 + q4 * 4] = *(const float4*)(kvp + q4 * 4);
        *(float4*)&vsh[t * 36 + q4 * 4] = *(const float4*)(kvp + 256 + q4 * 4);
    }

    float q[32];
    const float* qp = g_arena + OFF_Q + ((size_t)w_idx * 64 + t) * 256 + hh * 32;
    #pragma unroll
    for (int q4 = 0; q4 < 8; q4++) {
        float4 qq = *(const float4*)(qp + q4 * 4);
        q[q4*4+0] = qq.x; q[q4*4+1] = qq.y; q[q4*4+2] = qq.z; q[q4*4+3] = qq.w;
    }
    __syncthreads();

    int r1 = t >> 3, c1 = t & 7;
    int win = w_idx & 1023;
    const float* mrow = mask + ((size_t)win * 64 + t) * 64;

    float s[64];
    #pragma unroll
    for (int m = 0; m < 64; m++) {
        float acc = 0.f;
        #pragma unroll
        for (int d4 = 0; d4 < 8; d4++) {
            float4 kk = *(const float4*)&ksh[m * 36 + d4 * 4];
            acc += q[d4*4+0]*kk.x + q[d4*4+1]*kk.y + q[d4*4+2]*kk.z + q[d4*4+3]*kk.w;
        }
        int r2 = m >> 3, c2 = m & 7;
        s[m] = acc + sbias[(r1 - r2 + 7) * 15 + (c1 - c2 + 7)] + mrow[m];
    }

    float mx = -1e30f;
    #pragma unroll
    for (int m = 0; m < 64; m++) mx = fmaxf(mx, s[m]);
    float sum = 0.f;
    #pragma unroll
    for (int m = 0; m < 64; m++) { s[m] = __expf(s[m] - mx); sum += s[m]; }
    float inv = 1.f / sum;

    float o[32];
    #pragma unroll
    for (int j = 0; j < 32; j++) o[j] = 0.f;
    #pragma unroll
    for (int m = 0; m < 64; m++) {
        float p = s[m];
        #pragma unroll
        for (int d4 = 0; d4 < 8; d4++) {
            float4 vv = *(const float4*)&vsh[m * 36 + d4 * 4];
            o[d4*4+0] += p * vv.x; o[d4*4+1] += p * vv.y;
            o[d4*4+2] += p * vv.z; o[d4*4+3] += p * vv.w;
        }
    }

    // split-pack output (fp16 hi/lo planes)
    uint32_t* au = (uint32_t*)g_arena;
    size_t base = ((size_t)w_idx * 64 + t) * 256 + hh * 32;
    #pragma unroll
    for (int j = 0; j < 16; j++) {
        float a = o[2*j] * inv, b = o[2*j+1] * inv;
        __half ha, la, hb, lb;
        split2h(a, ha, la); split2h(b, hb, lb);
        size_t widx = (base >> 1) + j;
        au[OFF_ATTN_S + widx] =
            (uint32_t)__half_as_ushort(ha) | ((uint32_t)__half_as_ushort(hb) << 16);
        au[OFF_ATTN_S + 16777216 + widx] =
            (uint32_t)__half_as_ushort(la) | ((uint32_t)__half_as_ushort(lb) << 16);
    }
}

// ---------------------------------------------------------------------------
// Launch. 72KB dynamic smem (attribute opt-in, proven safe).
// ---------------------------------------------------------------------------
extern "C" void kernel_launch(void* const* d_in, const int* in_sizes, int n_in,
                              void* d_out, int out_size)
{
    const float* x     = (const float*)d_in[0];
    const float* maskm = (const float*)d_in[1];
    const float* g1    = (const float*)d_in[2];
    const float* b1    = (const float*)d_in[3];
    const float* qw    = (const float*)d_in[4];
    const float* qb    = (const float*)d_in[5];
    const float* kvw   = (const float*)d_in[6];
    const float* kvb   = (const float*)d_in[7];
    const float* pw    = (const float*)d_in[8];
    const float* pb    = (const float*)d_in[9];
    const float* btab  = (const float*)d_in[10];
    const float* g2    = (const float*)d_in[11];
    const float* b2    = (const float*)d_in[12];
    const float* w1    = (const float*)d_in[13];
    const float* bi1   = (const float*)d_in[14];
    const float* w2    = (const float*)d_in[15];
    const float* bi2   = (const float*)d_in[16];
    float* out = (float*)d_out;

    cudaFuncSetAttribute(mma_gemm<0,256>,  cudaFuncAttributeMaxDynamicSharedMemorySize, GSMEM);
    cudaFuncSetAttribute(mma_gemm<1,256>,  cudaFuncAttributeMaxDynamicSharedMemorySize, GSMEM);
    cudaFuncSetAttribute(mma_gemm<2,256>,  cudaFuncAttributeMaxDynamicSharedMemorySize, GSMEM);
    cudaFuncSetAttribute(mma_gemm<3,256>,  cudaFuncAttributeMaxDynamicSharedMemorySize, GSMEM);
    cudaFuncSetAttribute(mma_gemm<4,1024>, cudaFuncAttributeMaxDynamicSharedMemorySize, GSMEM);

    // 0) convert weights (single launch)
    wsplit_all<<<3072, 256>>>(qw, kvw, pw, w1, w2);

    // 1) LN1 + shift + window partition
    ln_window_kernel<<<MTOK, 256>>>(x, g1, b1);

    // 2) q projection (N=256)
    mma_gemm<0,256><<<dim3(2, 1024), 256, GSMEM>>>(qb, nullptr, nullptr);

    // 3) kv projection (N=512)
    mma_gemm<1,256><<<dim3(4, 1024), 256, GSMEM>>>(kvb, nullptr, nullptr);

    // 4) windowed attention
    attn_kernel<<<dim3(2048, 8), 64>>>(maskm, btab);

    // 5) output projection + residuals + scatter -> x1   (ncu -s 5 target)
    mma_gemm<2,256><<<dim3(2, 1024), 256, GSMEM>>>(pb, x, nullptr);

    // 6) LN2
    ln2_kernel<<<MTOK, 256>>>(g2, b2);

    // 7) MLP up + GELU (N=1024)
    mma_gemm<3,256><<<dim3(8, 1024), 256, GSMEM>>>(bi1, nullptr, nullptr);

    // 8) MLP down + residual -> out (K=1024)
    mma_gemm<4,1024><<<dim3(2, 1024), 256, GSMEM>>>(bi2, nullptr, out);
}

// round 13
// speedup vs baseline: 3.4141x; 1.3650x over previous
#include <cuda_runtime.h>
#include <cuda_bf16.h>
#include <cuda_fp16.h>
#include <math.h>
#include <stdint.h>

// ---------------------------------------------------------------------------
// Problem constants
// ---------------------------------------------------------------------------
#define HHs     256
#define WWs     256
#define CCs     256
#define WS_     8
#define SHIFT_  4
#define MTOK    131072
#define QSCALE  0.17677669529663689f  // 1/sqrt(32)

// ---------------------------------------------------------------------------
// Arena (u32 words). qin = two fp16 planes (hi for GEMM, hi+lo for residual);
// kvin/attn/xn2/hid = single fp16 plane; weights = single fp16 plane.
// ---------------------------------------------------------------------------
#define OFF_QIN_S  ((size_t)0)           // hi plane + lo plane (window order)
#define OFF_KVIN_S ((size_t)33554432)
#define OFF_Q      ((size_t)67108864)    // fp32
#define OFF_KV     ((size_t)100663296)   // fp32
#define OFF_ATTN_S ((size_t)167772160)   // single fp16 plane
#define OFF_X1     ((size_t)201326592)   // fp32 (image order)
#define OFF_XN2_S  ((size_t)234881024)   // single fp16 plane
#define OFF_HID_S  ((size_t)268435456)   // single fp16 plane (MTOK*1024 halves)
#define OFF_W      ((size_t)402653184)   // fp16 weights
#define ARENA_F    ((size_t)403439616)

__device__ float g_arena[ARENA_F];

// weight sub-offsets (u32 words) within OFF_W
#define WOFF_Q   0
#define WOFF_KV  65536
#define WOFF_P   196608
#define WOFF_W1  262144
#define WOFF_W2  524288

// ---------------------------------------------------------------------------
// Helpers (baseline PTX only)
// ---------------------------------------------------------------------------
__device__ __forceinline__ uint32_t s2u(const void* p) {
    uint32_t a;
    asm("{ .reg .u64 t; cvta.to.shared.u64 t, %1; cvt.u32.u64 %0, t; }" : "=r"(a) : "l"(p));
    return a;
}
__device__ __forceinline__ void cpa16(uint32_t saddr, const void* gptr) {
    asm volatile("cp.async.cg.shared.global [%0], [%1], 16;"
                 :: "r"(saddr), "l"(__cvta_generic_to_global(gptr)) : "memory");
}
__device__ __forceinline__ void cpa_commit() {
    asm volatile("cp.async.commit_group;" ::: "memory");
}
__device__ __forceinline__ void ldmx4(uint32_t* r, uint32_t addr) {
    asm volatile("ldmatrix.sync.aligned.m8n8.x4.shared.b16 {%0,%1,%2,%3}, [%4];"
                 : "=r"(r[0]), "=r"(r[1]), "=r"(r[2]), "=r"(r[3]) : "r"(addr));
}
__device__ __forceinline__ void mma16816h(float& c0, float& c1, float& c2, float& c3,
                                          uint32_t a0, uint32_t a1, uint32_t a2, uint32_t a3,
                                          uint32_t b0, uint32_t b1) {
    asm volatile(
        "mma.sync.aligned.m16n8k16.row.col.f32.f16.f16.f32 "
        "{%0,%1,%2,%3}, {%4,%5,%6,%7}, {%8,%9}, {%0,%1,%2,%3};"
        : "+f"(c0), "+f"(c1), "+f"(c2), "+f"(c3)
        : "r"(a0), "r"(a1), "r"(a2), "r"(a3), "r"(b0), "r"(b1));
}
__device__ __forceinline__ float h2f16(uint32_t u16v) {
    return __half2float(__ushort_as_half((unsigned short)u16v));
}
__device__ __forceinline__ void split2h(float v, __half& hi, __half& lo) {
    hi = __float2half(v);
    lo = __float2half(v - __half2float(hi));
}

// ---------------------------------------------------------------------------
// Weight convert: all 5 weights -> single fp16 plane, ONE launch.
// ---------------------------------------------------------------------------
__global__ void wsplit_all(const float* __restrict__ qw, const float* __restrict__ kvw,
                           const float* __restrict__ pw, const float* __restrict__ w1,
                           const float* __restrict__ w2) {
    int i = blockIdx.x * 256 + threadIdx.x;   // 0..786431
    const float* src; int woff, j = i;
    if (j < 65536)        { src = qw;  woff = WOFF_Q; }
    else if ((j -= 65536) < 131072) { src = kvw; woff = WOFF_KV; }
    else if ((j -= 131072) < 65536) { src = pw;  woff = WOFF_P; }
    else if ((j -= 65536) < 262144) { src = w1;  woff = WOFF_W1; }
    else { j -= 262144;               src = w2;  woff = WOFF_W2; }
    __half* hp = (__half*)((uint32_t*)g_arena + OFF_W + woff);
    hp[j] = __float2half(src[j]);
}

// ---------------------------------------------------------------------------
// LN1 + shift-roll + window partition.
// qin: hi + lo planes (lo needed only for the exact residual in MODE 2).
// kvin: hi plane only.
// ---------------------------------------------------------------------------
__global__ __launch_bounds__(256)
void ln_window_kernel(const float* __restrict__ x,
                      const float* __restrict__ g1,
                      const float* __restrict__ b1)
{
    int token = blockIdx.x, tid = threadIdx.x;
    int w_idx = token >> 6, n = token & 63;
    int b = w_idx >> 10, win = w_idx & 1023;
    int wh = win >> 5, wwc = win & 31;
    int r = n >> 3, cw = n & 7;
    int sh = (wh * WS_ + r + SHIFT_) & (HHs - 1);
    int sw = (wwc * WS_ + cw + SHIFT_) & (WWs - 1);

    __shared__ float red[16];
    float gg = g1[tid], bcoef = b1[tid];
    int warp = tid >> 5, lane = tid & 31;
    uint32_t* au = (uint32_t*)g_arena;

    for (int dsel = 0; dsel < 2; dsel++) {
        size_t base = ((((size_t)b * 2 + dsel) * HHs + sh) * WWs + sw) * CCs;
        float v = x[base + tid];
        float s = v, sq = v * v;
        #pragma unroll
        for (int o = 16; o; o >>= 1) {
            s  += __shfl_xor_sync(0xffffffffu, s,  o);
            sq += __shfl_xor_sync(0xffffffffu, sq, o);
        }
        if (lane == 0) { red[warp] = s; red[8 + warp] = sq; }
        __syncthreads();
        if (tid < 32) {
            float a = (tid < 8) ? red[tid] : 0.f;
            float c = (tid < 8) ? red[8 + tid] : 0.f;
            #pragma unroll
            for (int o = 4; o; o >>= 1) {
                a += __shfl_xor_sync(0xffffffffu, a, o);
                c += __shfl_xor_sync(0xffffffffu, c, o);
            }
            if (tid == 0) { red[0] = a; red[1] = c; }
        }
        __syncthreads();
        float mean = red[0] * (1.f / CCs);
        float var  = red[1] * (1.f / CCs) - mean * mean;
        float rstd = rsqrtf(var + 1e-5f);
        float outv = (v - mean) * rstd * gg + bcoef;
        size_t e = (size_t)token * CCs + tid;
        if (dsel == 0) {
            __half h, l;
            split2h(outv, h, l);
            __half* hp = (__half*)(au + OFF_QIN_S);
            hp[e] = h;
            hp[(size_t)MTOK * CCs + e] = l;
        } else {
            ((__half*)(au + OFF_KVIN_S))[e] = __float2half(outv);
        }
        __syncthreads();
    }
}

// ---------------------------------------------------------------------------
// LN2: x1 fp32 -> xn2 single fp16 plane
// ---------------------------------------------------------------------------
__global__ __launch_bounds__(256)
void ln2_kernel(const float* __restrict__ g2, const float* __restrict__ b2)
{
    int token = blockIdx.x, tid = threadIdx.x;
    __shared__ float red[16];
    size_t base = (size_t)token * CCs;
    float v = g_arena[OFF_X1 + base + tid];
    float s = v, sq = v * v;
    #pragma unroll
    for (int o = 16; o; o >>= 1) {
        s  += __shfl_xor_sync(0xffffffffu, s,  o);
        sq += __shfl_xor_sync(0xffffffffu, sq, o);
    }
    int warp = tid >> 5, lane = tid & 31;
    if (lane == 0) { red[warp] = s; red[8 + warp] = sq; }
    __syncthreads();
    if (tid < 32) {
        float a = (tid < 8) ? red[tid] : 0.f;
        float c = (tid < 8) ? red[8 + tid] : 0.f;
        #pragma unroll
        for (int o = 4; o; o >>= 1) {
            a += __shfl_xor_sync(0xffffffffu, a, o);
            c += __shfl_xor_sync(0xffffffffu, c, o);
        }
        if (tid == 0) { red[0] = a; red[1] = c; }
    }
    __syncthreads();
    float mean = red[0] * (1.f / CCs);
    float var  = red[1] * (1.f / CCs) - mean * mean;
    float rstd = rsqrtf(var + 1e-5f);
    float outv = (v - mean) * rstd * g2[tid] + b2[tid];
    ((__half*)((uint32_t*)g_arena + OFF_XN2_S))[base + tid] = __float2half(outv);
}

// ---------------------------------------------------------------------------
// Single-pass fp16 warp-MMA GEMM: out = A_fp16 * B_fp16 (fp32 accum).
// CTA 128x128, BK=16, 8 warps (warp tile 64x32).
// 4-stage cp.async pipeline, one __syncthreads per chunk.
// Per chunk: 6 LDSM (4 A + 2 B), 16 HMMA.
// ---------------------------------------------------------------------------
#define PLANE_B 6144        // 128 rows * 48 B (stride 24 halves)
#define STG_B   12288       // A | B
#define NSTAGE  4
#define GSMEM   (NSTAGE * STG_B) // 49152

template<int MODE, int KDIM>
__global__ __launch_bounds__(256, 2)
void mma_gemm(const float* __restrict__ bias,
              const float* __restrict__ xsrc,
              float* __restrict__ dout)
{
    constexpr int NC = KDIM / 16;
    constexpr size_t AOFF = (MODE == 0) ? OFF_QIN_S : (MODE == 1) ? OFF_KVIN_S :
                            (MODE == 2) ? OFF_ATTN_S : (MODE == 3) ? OFF_XN2_S : OFF_HID_S;
    constexpr size_t WO = OFF_W + ((MODE == 0) ? WOFF_Q : (MODE == 1) ? WOFF_KV :
                                   (MODE == 2) ? WOFF_P : (MODE == 3) ? WOFF_W1 : WOFF_W2);

    extern __shared__ char smem[];
    uint32_t sbase = s2u(smem);

    int tid = threadIdx.x;
    int wid = tid >> 5, lane = tid & 31;
    int g = lane >> 2, tg = lane & 3;
    int warpM = wid & 1, warpN = wid >> 1;
    int m0 = blockIdx.y * 128;
    int n0 = blockIdx.x * 128;

    uint32_t* au = (uint32_t*)g_arena;
    const __half* Ah = (const __half*)(au + AOFF);
    const __half* Bw = (const __half*)(au + WO);

    float acc[4][4][4];
    #pragma unroll
    for (int i = 0; i < 4; i++)
        #pragma unroll
        for (int j = 0; j < 4; j++)
            #pragma unroll
            for (int k = 0; k < 4; k++) acc[i][j][k] = 0.f;

    int l7 = lane & 7;
    int a_row = warpM * 64 + l7 + ((lane >> 3) & 1) * 8;   // + mt*16
    int a_kof = (lane >> 4) * 8;
    int b_row = warpN * 32 + l7 + ((lane >> 4) & 1) * 8;   // + pair*16
    int b_kof = ((lane >> 3) & 1) * 8;

    auto load_chunk = [&](int s, int kc0) {
        uint32_t sb = sbase + s * STG_B;
        int row = tid >> 1, k8 = (tid & 1) * 8;
        uint32_t so = sb + row * 48 + k8 * 2;
        size_t ga = (size_t)(m0 + row) * KDIM + kc0 + k8;
        size_t gb = (size_t)(n0 + row) * KDIM + kc0 + k8;
        cpa16(so,           Ah + ga);
        cpa16(so + PLANE_B, Bw + gb);
        cpa_commit();
    };

    auto compute = [&](int s) {
        uint32_t stg = sbase + s * STG_B;
        uint32_t b[4][2];
        {
            uint32_t bB = stg + PLANE_B;
            uint32_t t4[4];
            ldmx4(t4, bB + (b_row * 24 + b_kof) * 2);
            b[0][0] = t4[0]; b[0][1] = t4[1]; b[1][0] = t4[2]; b[1][1] = t4[3];
            ldmx4(t4, bB + ((b_row + 16) * 24 + b_kof) * 2);
            b[2][0] = t4[0]; b[2][1] = t4[1]; b[3][0] = t4[2]; b[3][1] = t4[3];
        }
        uint32_t a[4][4];
        #pragma unroll
        for (int mt = 0; mt < 4; mt++)
            ldmx4(a[mt], stg + ((a_row + mt * 16) * 24 + a_kof) * 2);
        #pragma unroll
        for (int mt = 0; mt < 4; mt++)
            #pragma unroll
            for (int nt = 0; nt < 4; nt++)
                mma16816h(acc[mt][nt][0], acc[mt][nt][1], acc[mt][nt][2], acc[mt][nt][3],
                          a[mt][0], a[mt][1], a[mt][2], a[mt][3],
                          b[nt][0], b[nt][1]);
    };

    load_chunk(0, 0);
    load_chunk(1, 16);
    load_chunk(2, 32);
    for (int c = 0; c < NC; c++) {
        asm volatile("cp.async.wait_group 2;" ::: "memory");
        __syncthreads();
        if (c + 3 < NC) load_chunk((c + 3) & 3, (c + 3) * 16);
        else            cpa_commit();
        compute(c & 3);
    }

    // ------------------------------- epilogue -------------------------------
    int tg2 = tg * 2;
    int coln[4];
    float2 bb[4];
    #pragma unroll
    for (int nt = 0; nt < 4; nt++) {
        coln[nt] = n0 + warpN * 32 + nt * 8 + tg2;
        bb[nt] = *(const float2*)(bias + coln[nt]);
    }

    #pragma unroll
    for (int mt = 0; mt < 4; mt++) {
        #pragma unroll
        for (int rr = 0; rr < 2; rr++) {
            int row = m0 + warpM * 64 + mt * 16 + g + rr * 8;

            size_t img = 0, ximg = 0;
            if (MODE == 2) {
                int w_idx = row >> 6, nn = row & 63;
                int b = w_idx >> 10, win = w_idx & 1023;
                int wh = win >> 5, wwc = win & 31;
                int r = nn >> 3, cw = nn & 7;
                int hi_ = (wh * WS_ + r + SHIFT_) & (HHs - 1);
                int wi_ = (wwc * WS_ + cw + SHIFT_) & (WWs - 1);
                img  = (((size_t)b * HHs + hi_) * WWs + wi_) * CCs;
                ximg = ((((size_t)b * 2) * HHs + hi_) * WWs + wi_) * CCs;
            }

            #pragma unroll
            for (int nt = 0; nt < 4; nt++) {
                int col = coln[nt];
                float v0 = acc[mt][nt][rr * 2 + 0] + bb[nt].x;
                float v1 = acc[mt][nt][rr * 2 + 1] + bb[nt].y;

                if (MODE == 0) {
                    *(float2*)(g_arena + OFF_Q + (size_t)row * 256 + col) =
                        make_float2(v0 * QSCALE, v1 * QSCALE);
                } else if (MODE == 1) {
                    *(float2*)(g_arena + OFF_KV + (size_t)row * 512 + col) =
                        make_float2(v0, v1);
                } else if (MODE == 2) {
                    size_t widx = (size_t)row * 128 + (col >> 1);
                    uint32_t hq = au[OFF_QIN_S + widx];
                    uint32_t lq = au[OFF_QIN_S + 16777216 + widx];
                    float2 sc = *(const float2*)(xsrc + ximg + col);
                    v0 += h2f16(hq & 0xFFFFu) + h2f16(lq & 0xFFFFu) + sc.x;
                    v1 += h2f16(hq >> 16)     + h2f16(lq >> 16)     + sc.y;
                    *(float2*)(g_arena + OFF_X1 + img + col) = make_float2(v0, v1);
                } else if (MODE == 3) {
                    float g0 = v0 * normcdff(v0);
                    float g1 = v1 * normcdff(v1);
                    size_t widx = (size_t)row * 512 + (col >> 1);
                    au[OFF_HID_S + widx] =
                        (uint32_t)__half_as_ushort(__float2half(g0)) |
                        ((uint32_t)__half_as_ushort(__float2half(g1)) << 16);
                } else { // MODE 4
                    float2 x1v = *(const float2*)(g_arena + OFF_X1 + (size_t)row * 256 + col);
                    *(float2*)(dout + (size_t)row * 256 + col) =
                        make_float2(v0 + x1v.x, v1 + x1v.y);
                }
            }
        }
    }
}

// ---------------------------------------------------------------------------
// Windowed attention. Reads q/kv fp32, writes attn single fp16 plane.
// ---------------------------------------------------------------------------
__global__ __launch_bounds__(64)
void attn_kernel(const float* __restrict__ mask, const float* __restrict__ btab)
{
    int w_idx = blockIdx.x, hh = blockIdx.y, t = threadIdx.x;
    __shared__ float ksh[64 * 36];
    __shared__ float vsh[64 * 36];
    __shared__ float sbias[225];

    for (int i = t; i < 225; i += 64) sbias[i] = btab[i * 8 + hh];

    const float* kvp = g_arena + OFF_KV + ((size_t)w_idx * 64 + t) * 512 + hh * 32;
    #pragma unroll
    for (int q4 = 0; q4 < 8; q4++) {
        *(float4*)&ksh[t * 36 + q4 * 4] = *(const float4*)(kvp + q4 * 4);
        *(float4*)&vsh[t * 36 + q4 * 4] = *(const float4*)(kvp + 256 + q4 * 4);
    }

    float q[32];
    const float* qp = g_arena + OFF_Q + ((size_t)w_idx * 64 + t) * 256 + hh * 32;
    #pragma unroll
    for (int q4 = 0; q4 < 8; q4++) {
        float4 qq = *(const float4*)(qp + q4 * 4);
        q[q4*4+0] = qq.x; q[q4*4+1] = qq.y; q[q4*4+2] = qq.z; q[q4*4+3] = qq.w;
    }
    __syncthreads();

    int r1 = t >> 3, c1 = t & 7;
    int win = w_idx & 1023;
    const float* mrow = mask + ((size_t)win * 64 + t) * 64;

    float s[64];
    #pragma unroll
    for (int m = 0; m < 64; m++) {
        float acc = 0.f;
        #pragma unroll
        for (int d4 = 0; d4 < 8; d4++) {
            float4 kk = *(const float4*)&ksh[m * 36 + d4 * 4];
            acc += q[d4*4+0]*kk.x + q[d4*4+1]*kk.y + q[d4*4+2]*kk.z + q[d4*4+3]*kk.w;
        }
        int r2 = m >> 3, c2 = m & 7;
        s[m] = acc + sbias[(r1 - r2 + 7) * 15 + (c1 - c2 + 7)] + mrow[m];
    }

    float mx = -1e30f;
    #pragma unroll
    for (int m = 0; m < 64; m++) mx = fmaxf(mx, s[m]);
    float sum = 0.f;
    #pragma unroll
    for (int m = 0; m < 64; m++) { s[m] = __expf(s[m] - mx); sum += s[m]; }
    float inv = 1.f / sum;

    float o[32];
    #pragma unroll
    for (int j = 0; j < 32; j++) o[j] = 0.f;
    #pragma unroll
    for (int m = 0; m < 64; m++) {
        float p = s[m];
        #pragma unroll
        for (int d4 = 0; d4 < 8; d4++) {
            float4 vv = *(const float4*)&vsh[m * 36 + d4 * 4];
            o[d4*4+0] += p * vv.x; o[d4*4+1] += p * vv.y;
            o[d4*4+2] += p * vv.z; o[d4*4+3] += p * vv.w;
        }
    }

    // single fp16 plane output
    uint32_t* au = (uint32_t*)g_arena;
    size_t base = ((size_t)w_idx * 64 + t) * 256 + hh * 32;
    #pragma unroll
    for (int j = 0; j < 16; j++) {
        float a = o[2*j] * inv, b = o[2*j+1] * inv;
        au[OFF_ATTN_S + (base >> 1) + j] =
            (uint32_t)__half_as_ushort(__float2half(a)) |
            ((uint32_t)__half_as_ushort(__float2half(b)) << 16);
    }
}

// ---------------------------------------------------------------------------
// Launch. 48KB dynamic smem.
// ---------------------------------------------------------------------------
extern "C" void kernel_launch(void* const* d_in, const int* in_sizes, int n_in,
                              void* d_out, int out_size)
{
    const float* x     = (const float*)d_in[0];
    const float* maskm = (const float*)d_in[1];
    const float* g1    = (const float*)d_in[2];
    const float* b1    = (const float*)d_in[3];
    const float* qw    = (const float*)d_in[4];
    const float* qb    = (const float*)d_in[5];
    const float* kvw   = (const float*)d_in[6];
    const float* kvb   = (const float*)d_in[7];
    const float* pw    = (const float*)d_in[8];
    const float* pb    = (const float*)d_in[9];
    const float* btab  = (const float*)d_in[10];
    const float* g2    = (const float*)d_in[11];
    const float* b2    = (const float*)d_in[12];
    const float* w1    = (const float*)d_in[13];
    const float* bi1   = (const float*)d_in[14];
    const float* w2    = (const float*)d_in[15];
    const float* bi2   = (const float*)d_in[16];
    float* out = (float*)d_out;

    // 0) convert weights (single launch)
    wsplit_all<<<3072, 256>>>(qw, kvw, pw, w1, w2);

    // 1) LN1 + shift + window partition
    ln_window_kernel<<<MTOK, 256>>>(x, g1, b1);

    // 2) q projection (N=256)
    mma_gemm<0,256><<<dim3(2, 1024), 256, GSMEM>>>(qb, nullptr, nullptr);

    // 3) kv projection (N=512)
    mma_gemm<1,256><<<dim3(4, 1024), 256, GSMEM>>>(kvb, nullptr, nullptr);

    // 4) windowed attention
    attn_kernel<<<dim3(2048, 8), 64>>>(maskm, btab);

    // 5) output projection + residuals + scatter -> x1   (ncu -s 5 target)
    mma_gemm<2,256><<<dim3(2, 1024), 256, GSMEM>>>(pb, x, nullptr);

    // 6) LN2
    ln2_kernel<<<MTOK, 256>>>(g2, b2);

    // 7) MLP up + GELU (N=1024)
    mma_gemm<3,256><<<dim3(8, 1024), 256, GSMEM>>>(bi1, nullptr, nullptr);

    // 8) MLP down + residual -> out (K=1024)
    mma_gemm<4,1024><<<dim3(2, 1024), 256, GSMEM>>>(bi2, nullptr, out);
}